// round 12
// baseline (speedup 1.0000x reference)
#include <cuda_runtime.h>
#include <cuda_fp16.h>
#include <math.h>

// ---------------- problem constants ----------------
#define N_P 100000
#define N_D 1000
#define N_S 5000
#define NT  (N_P + N_D + N_S)
#define CD  64
#define HD  4
#define E0 300000
#define E1 300000
#define E2 100000
#define E3 100000
#define ET (E0 + E1 + E2 + E3)
#define KREL_TOT (2*N_P + 2*N_D)
#define DSTN_TOT (N_D + N_P + 2*N_S)
#define XP 68   // Xs row pitch (floats)
#define WTP 68  // transposed-W row pitch (>=64 extent; 68%32=4 -> conflict-free reads)
#define ZB 222
#define DEN4 (DSTN_TOT)
#define NUM4 (DSTN_TOT * 16)
#define TOT4 (DEN4 + NUM4)

typedef unsigned long long u64;

// ---------------- device scratch ----------------
__device__ __align__(16) float  g_x[NT * CD];
__device__ __align__(16) __half g_qh[NT * CD];
__device__ __align__(16) __half g_kh[KREL_TOT * CD];
__device__ __align__(16) __half g_vh[KREL_TOT * CD];
__device__ __align__(16) float  g_den[DSTN_TOT * HD];
__device__ __align__(16) float  g_num[DSTN_TOT * CD];
__device__ __align__(16) float  g_Wc[16 * CD * CD];
__device__ __align__(16) float  g_bc[16 * CD];

// ---------------- helpers ----------------
__device__ __forceinline__ u64 pack2(float x) {
    u64 r; asm("mov.b64 %0, {%1, %1};" : "=l"(r) : "f"(x)); return r;
}
__device__ __forceinline__ u64 fma2(u64 a, u64 b, u64 c) {
    u64 d; asm("fma.rn.f32x2 %0, %1, %2, %3;" : "=l"(d) : "l"(a), "l"(b), "l"(c)); return d;
}
__device__ __forceinline__ float2 unpack2(u64 a) {
    float2 f; asm("mov.b64 {%0, %1}, %2;" : "=f"(f.x), "=f"(f.y) : "l"(a)); return f;
}
__device__ __forceinline__ float tf32r(float x) {   // round-to-nearest tf32
    unsigned r; asm("cvt.rna.tf32.f32 %0, %1;" : "=r"(r) : "f"(x));
    return __uint_as_float(r);
}

// ---------------- TF32 warp-MMA core: 128x64 @ 64x64 ----------------
// Xs: tf32-rounded A tile [128][XP]; Wt: tf32-rounded, transposed B [64][WTP].
// Each of 4 warps computes 32 rows; per-thread result acc[2][8][4].
__device__ __forceinline__ void tf32_mma(const float* Xs, const float* Wt,
                                         int rb, int gid, int tidg,
                                         float acc[2][8][4])
{
#pragma unroll
    for (int k0 = 0; k0 < 64; k0 += 8) {
        unsigned a[2][4];
#pragma unroll
        for (int mt = 0; mt < 2; mt++) {
            const float* xp = &Xs[(rb + mt * 16 + gid) * XP + k0 + tidg];
            a[mt][0] = __float_as_uint(xp[0]);
            a[mt][1] = __float_as_uint(xp[8 * XP]);
            a[mt][2] = __float_as_uint(xp[4]);
            a[mt][3] = __float_as_uint(xp[8 * XP + 4]);
        }
        unsigned b[8][2];
#pragma unroll
        for (int nt = 0; nt < 8; nt++) {
            const float* wp = &Wt[(nt * 8 + gid) * WTP + k0 + tidg];
            b[nt][0] = __float_as_uint(wp[0]);
            b[nt][1] = __float_as_uint(wp[4]);
        }
#pragma unroll
        for (int mt = 0; mt < 2; mt++)
#pragma unroll
            for (int nt = 0; nt < 8; nt++)
                asm volatile(
                    "mma.sync.aligned.m16n8k8.row.col.f32.tf32.tf32.f32 "
                    "{%0,%1,%2,%3}, {%4,%5,%6,%7}, {%8,%9}, {%0,%1,%2,%3};"
                    : "+f"(acc[mt][nt][0]), "+f"(acc[mt][nt][1]),
                      "+f"(acc[mt][nt][2]), "+f"(acc[mt][nt][3])
                    : "r"(a[mt][0]), "r"(a[mt][1]), "r"(a[mt][2]), "r"(a[mt][3]),
                      "r"(b[nt][0]), "r"(b[nt][1]));
    }
}

// ---------------- fp32 FFMA2 GEMM core (input proj only) ----------------
__device__ __forceinline__ void mma_core(const float* Xs, const float* Ws,
                                         int ty, int tx, u64 acc[8][4])
{
#pragma unroll 2
    for (int kk = 0; kk < 64; kk += 4) {
        float4 xv[8];
#pragma unroll
        for (int i = 0; i < 8; i++)
            xv[i] = *(const float4*)&Xs[(ty + i * 16) * XP + kk];
#pragma unroll
        for (int c = 0; c < 4; c++) {
            ulonglong2 wA = *(const ulonglong2*)&Ws[(kk + c) * 64 + tx * 8];
            ulonglong2 wB = *(const ulonglong2*)&Ws[(kk + c) * 64 + tx * 8 + 4];
            u64 w0 = wA.x, w1 = wA.y, w2 = wB.x, w3 = wB.y;
#pragma unroll
            for (int i = 0; i < 8; i++) {
                float xs = (c == 0) ? xv[i].x : (c == 1) ? xv[i].y
                         : (c == 2) ? xv[i].z : xv[i].w;
                u64 x2 = pack2(xs);
                acc[i][0] = fma2(x2, w0, acc[i][0]);
                acc[i][1] = fma2(x2, w1, acc[i][1]);
                acc[i][2] = fma2(x2, w2, acc[i][2]);
                acc[i][3] = fma2(x2, w3, acc[i][3]);
            }
        }
    }
}

// ---------------- combine weights ----------------
__global__ void combine_weights(const float* __restrict__ Wk, const float* __restrict__ bk,
                                const float* __restrict__ Wv, const float* __restrict__ bv,
                                const float* __restrict__ a_rel, const float* __restrict__ m_rel,
                                const float* __restrict__ p_rel)
{
    int blk = blockIdx.x;
    int l  = blk >> 3;
    int kv = (blk >> 2) & 1;
    int r  = blk & 3;
    const int st_tab[4] = {0, 1, 1, 0};
    int st = st_tab[r];

    const float* Wbase = (kv == 0 ? Wk : Wv) + (size_t)(l*3 + st) * CD * CD;
    const float* bbase = (kv == 0 ? bk : bv) + (size_t)(l*3 + st) * CD;
    const float* rel   = (kv == 0 ? a_rel : m_rel) + (size_t)(l*4 + r) * HD * 256;

    __shared__ float srel[HD * 256];
    __shared__ float sscale[HD];
    int t = threadIdx.x; // 256
    for (int i = t; i < HD*256; i += 256) srel[i] = rel[i];
    if (t < HD) sscale[t] = (kv == 0) ? p_rel[(l*4 + r) * HD + t] * 0.25f : 1.0f;
    __syncthreads();

    float* Wc = g_Wc + (size_t)blk * CD * CD;
    float* bc = g_bc + (size_t)blk * CD;

    int c = t >> 2, h = t & 3;
    float wrow[16];
#pragma unroll
    for (int d = 0; d < 16; d++) wrow[d] = Wbase[c*CD + h*16 + d];
    float sc = sscale[h];
#pragma unroll
    for (int e = 0; e < 16; e++) {
        float s = 0.f;
#pragma unroll
        for (int d = 0; d < 16; d++) s += wrow[d] * srel[h*256 + d*16 + e];
        Wc[c*CD + h*16 + e] = s * sc;
    }
    if (t < CD) {
        int hh = t >> 4, ee = t & 15;
        float s = 0.f;
#pragma unroll
        for (int d = 0; d < 16; d++) s += bbase[hh*16 + d] * srel[hh*256 + d*16 + ee];
        bc[t] = s * sscale[hh];
    }
}

// ---------------- job descriptors ----------------
struct TileW { const float* W; const float* b; __half* Y; };
struct JobA  { const float* X; int M; int blk0; int nT; TileW tl[5]; };
struct ParamsA { JobA job[3]; int nblk_gemm; };

struct JobE {
    const float* num0; const float* den0;
    const float* num1; const float* den1;
    const float* xold; const float* skipp;
    const float* W; const float* b; float* Y;
    int M; int blk0;
};
struct ParamsE { JobE job[3]; };

struct JobI { const float* X; const float* W; const float* b; float* Y; int M; int blk0; int K; };
struct ParamsI { JobI job[3]; };

// ---------------- Phase A: TF32 -> fp16 outputs + fused zeroing ----------------
__global__ void __launch_bounds__(128)
gemm_phaseA(ParamsA P)
{
    __shared__ float Xs[128 * XP];
    __shared__ float Wt[64 * WTP];
    int bx = blockIdx.x;
    int t = threadIdx.x;

    if (bx >= P.nblk_gemm) {
        int zb = bx - P.nblk_gemm;
        float4 z = make_float4(0.f, 0.f, 0.f, 0.f);
        float4* dp = (float4*)g_den;
        float4* np = (float4*)g_num;
        for (int i = zb * 128 + t; i < TOT4; i += ZB * 128) {
            if (i < DEN4) dp[i] = z;
            else          np[i - DEN4] = z;
        }
        return;
    }

    int j = (bx >= P.job[2].blk0) ? 2 : (bx >= P.job[1].blk0) ? 1 : 0;
    const JobA& J = P.job[j];
    int m0 = (bx - J.blk0) * 128;
    const int lane = t & 31, warp = t >> 5;
    const int gid = lane >> 2, tidg = lane & 3;
    const int rb = warp * 32;

#pragma unroll
    for (int i = 0; i < 16; i++) {
        int f4 = t + i * 128;
        int row = f4 >> 4, c4 = f4 & 15;
        float4 v = make_float4(0.f, 0.f, 0.f, 0.f);
        if (m0 + row < J.M) v = *(const float4*)&J.X[(size_t)(m0 + row) * 64 + c4 * 4];
        v.x = tf32r(v.x); v.y = tf32r(v.y); v.z = tf32r(v.z); v.w = tf32r(v.w);
        *(float4*)&Xs[row * XP + c4 * 4] = v;
    }

    for (int ti = 0; ti < J.nT; ti++) {
        __syncthreads();
        const float* __restrict__ W = J.tl[ti].W;
#pragma unroll 8
        for (int i = 0; i < 32; i++) {
            int idx = t + i * 128;
            int k = idx >> 6, n = idx & 63;
            Wt[n * WTP + k] = tf32r(W[idx]);
        }
        __syncthreads();

        float acc[2][8][4];
#pragma unroll
        for (int mt = 0; mt < 2; mt++)
#pragma unroll
            for (int nt = 0; nt < 8; nt++)
#pragma unroll
                for (int r = 0; r < 4; r++) acc[mt][nt][r] = 0.f;

        tf32_mma(Xs, Wt, rb, gid, tidg, acc);

        const float* bias = J.tl[ti].b;
        __half* Y = J.tl[ti].Y;
        float bb[16];
#pragma unroll
        for (int nt = 0; nt < 8; nt++) {
            bb[2*nt]     = bias[nt * 8 + tidg * 2];
            bb[2*nt + 1] = bias[nt * 8 + tidg * 2 + 1];
        }
#pragma unroll
        for (int mt = 0; mt < 2; mt++) {
#pragma unroll
            for (int rr = 0; rr < 2; rr++) {
                int row = m0 + rb + mt * 16 + rr * 8 + gid;
                if (row < J.M) {
#pragma unroll
                    for (int nt = 0; nt < 8; nt++) {
                        float v0 = acc[mt][nt][2*rr]     + bb[2*nt];
                        float v1 = acc[mt][nt][2*rr + 1] + bb[2*nt + 1];
                        *(__half2*)&Y[(size_t)row * 64 + nt * 8 + tidg * 2] =
                            __floats2half2_rn(v0, v1);
                    }
                }
            }
        }
    }
}

// ---------------- Epilogue: TF32 gelu(softmax) @ Wa + skip gate (fp32 out) ----------------
__global__ void __launch_bounds__(128)
gemm_epilogue(ParamsE P)
{
    __shared__ float Xs[128 * XP];
    __shared__ float Wt[64 * WTP];
    int bx = blockIdx.x;
    int j = (bx >= P.job[2].blk0) ? 2 : (bx >= P.job[1].blk0) ? 1 : 0;
    const JobE& J = P.job[j];
    int m0 = (bx - J.blk0) * 128;
    int t = threadIdx.x;
    const int lane = t & 31, warp = t >> 5;
    const int gid = lane >> 2, tidg = lane & 3;
    const int rb = warp * 32;

    // build gelu(num/den) tile, tf32-rounded
#pragma unroll
    for (int i = 0; i < 64; i++) {
        int idx = t + i * 128;
        int row = idx >> 6, cc = idx & 63;
        float val = 0.f;
        int n = m0 + row;
        if (n < J.M) {
            int h = cc >> 4;
            val = J.num0[(size_t)n * 64 + cc] / (J.den0[(size_t)n * 4 + h] + 1e-16f);
            if (J.num1)
                val += J.num1[(size_t)n * 64 + cc] / (J.den1[(size_t)n * 4 + h] + 1e-16f);
            val = 0.5f * val * (1.0f + erff(val * 0.70710678118654752f));
        }
        Xs[row * XP + cc] = tf32r(val);
    }
#pragma unroll 8
    for (int i = 0; i < 32; i++) {
        int idx = t + i * 128;
        int k = idx >> 6, n = idx & 63;
        Wt[n * WTP + k] = tf32r(J.W[idx]);
    }
    __syncthreads();

    float acc[2][8][4];
#pragma unroll
    for (int mt = 0; mt < 2; mt++)
#pragma unroll
        for (int nt = 0; nt < 8; nt++)
#pragma unroll
            for (int r = 0; r < 4; r++) acc[mt][nt][r] = 0.f;

    tf32_mma(Xs, Wt, rb, gid, tidg, acc);

    float bb[16];
#pragma unroll
    for (int nt = 0; nt < 8; nt++) {
        bb[2*nt]     = J.b[nt * 8 + tidg * 2];
        bb[2*nt + 1] = J.b[nt * 8 + tidg * 2 + 1];
    }
    float s = 1.0f / (1.0f + expf(-J.skipp[0]));
    float om = 1.0f - s;

#pragma unroll
    for (int mt = 0; mt < 2; mt++) {
#pragma unroll
        for (int rr = 0; rr < 2; rr++) {
            int row = m0 + rb + mt * 16 + rr * 8 + gid;
            if (row < J.M) {
#pragma unroll
                for (int nt = 0; nt < 8; nt++) {
                    float2 xo = *(const float2*)&J.xold[(size_t)row * 64 + nt * 8 + tidg * 2];
                    float v0 = s * (acc[mt][nt][2*rr]     + bb[2*nt])     + om * xo.x;
                    float v1 = s * (acc[mt][nt][2*rr + 1] + bb[2*nt + 1]) + om * xo.y;
                    *(float2*)&J.Y[(size_t)row * 64 + nt * 8 + tidg * 2] = make_float2(v0, v1);
                }
            }
        }
    }
}

// ---------------- Input projections (128 thr, runtime K, fp32) ----------------
__global__ void __launch_bounds__(128)
gemm_input(ParamsI P)
{
    __shared__ float Xs[128 * XP];
    __shared__ __align__(16) float Ws[64 * 64];
    int bx = blockIdx.x;
    int j = (bx >= P.job[2].blk0) ? 2 : (bx >= P.job[1].blk0) ? 1 : 0;
    const JobI& J = P.job[j];
    int m0 = (bx - J.blk0) * 128;
    int t = threadIdx.x;
    const int ty = t >> 3, tx = t & 7;
    const int K = J.K;

    u64 acc[8][4];
#pragma unroll
    for (int i = 0; i < 8; i++)
#pragma unroll
        for (int k = 0; k < 4; k++) acc[i][k] = 0ull;

    for (int k0 = 0; k0 < K; k0 += 64) {
        __syncthreads();
#pragma unroll
        for (int i = 0; i < 16; i++) {
            int f4 = t + i * 128;
            int row = f4 >> 4, c4 = f4 & 15;
            float4 v = make_float4(0.f, 0.f, 0.f, 0.f);
            if (m0 + row < J.M) v = *(const float4*)&J.X[(size_t)(m0 + row) * K + k0 + c4 * 4];
            *(float4*)&Xs[row * XP + c4 * 4] = v;
        }
#pragma unroll
        for (int i = 0; i < 8; i++) {
            int f4 = (t + i * 128) * 4;
            *(float4*)&Ws[f4] = *(const float4*)&J.W[(size_t)k0 * 64 + f4];
        }
        __syncthreads();
        mma_core(Xs, Ws, ty, tx, acc);
    }

    float bb[8];
#pragma unroll
    for (int q = 0; q < 8; q++) bb[q] = J.b[tx * 8 + q];
#pragma unroll
    for (int i = 0; i < 8; i++) {
        int row = m0 + ty + i * 16;
        if (row < J.M) {
            float o[8];
#pragma unroll
            for (int k = 0; k < 4; k++) {
                float2 p = unpack2(acc[i][k]);
                o[2*k] = p.x + bb[2*k]; o[2*k+1] = p.y + bb[2*k+1];
            }
            *(float4*)&J.Y[(size_t)row * 64 + tx * 8]     = make_float4(o[0], o[1], o[2], o[3]);
            *(float4*)&J.Y[(size_t)row * 64 + tx * 8 + 4] = make_float4(o[4], o[5], o[6], o[7]);
        }
    }
}

// ---------------- merged single-pass edge kernel (fp16 gathers, fp32 math) ----------------
__global__ void edge_all(const int* __restrict__ ei0, const int* __restrict__ ei1,
                         const int* __restrict__ ei2, const int* __restrict__ ei3)
{
    int gid = blockIdx.x * blockDim.x + threadIdx.x;
    if (gid >= ET * HD) return;
    int e = gid >> 2, h = gid & 3;

    const int* ei; int er, E, kvoff, qoff, dnoff;
    if (e < E0)                 { ei = ei0; er = e;            E = E0; kvoff = 0;           qoff = N_P;     dnoff = 0; }
    else if (e < E0+E1)         { ei = ei1; er = e - E0;       E = E1; kvoff = N_P;         qoff = 0;       dnoff = N_D; }
    else if (e < E0+E1+E2)      { ei = ei2; er = e - (E0+E1);  E = E2; kvoff = N_P+N_D;     qoff = N_P+N_D; dnoff = N_D+N_P; }
    else                        { ei = ei3; er = e-(E0+E1+E2); E = E3; kvoff = N_P+2*N_D;   qoff = N_P+N_D; dnoff = N_D+N_P+N_S; }

    int src = __ldg(&ei[er]);
    int dst = __ldg(&ei[E + er]);

    const uint4* qp = (const uint4*)&g_qh[(size_t)(qoff + dst) * 64 + h * 16];
    const uint4* kp = (const uint4*)&g_kh[(size_t)(kvoff + src) * 64 + h * 16];
    const uint4* vp = (const uint4*)&g_vh[(size_t)(kvoff + src) * 64 + h * 16];

    __half2 qv[8], kv[8], vv[8];
    *(uint4*)&qv[0] = qp[0]; *(uint4*)&qv[4] = qp[1];
    *(uint4*)&kv[0] = kp[0]; *(uint4*)&kv[4] = kp[1];
    *(uint4*)&vv[0] = vp[0]; *(uint4*)&vv[4] = vp[1];

    float a = 0.f;
#pragma unroll
    for (int jj = 0; jj < 8; jj++) {
        float2 qf = __half22float2(qv[jj]);
        float2 kf = __half22float2(kv[jj]);
        a += qf.x * kf.x + qf.y * kf.y;
    }
    float w = __expf(fminf(a, 60.f));
    atomicAdd(&g_den[(size_t)(dnoff + dst) * 4 + h], w);

    float4* np = (float4*)&g_num[(size_t)(dnoff + dst) * 64 + h * 16];
#pragma unroll
    for (int jj = 0; jj < 4; jj++) {
        float2 v0 = __half22float2(vv[2*jj]);
        float2 v1 = __half22float2(vv[2*jj + 1]);
        atomicAdd(&np[jj], make_float4(v0.x * w, v0.y * w, v1.x * w, v1.y * w));
    }
}

// ---------------- host orchestration ----------------
static inline int cdiv(int a, int b) { return (a + b - 1) / b; }

extern "C" void kernel_launch(void* const* d_in, const int* in_sizes, int n_in,
                              void* d_out, int out_size)
{
    const float* x_p   = (const float*)d_in[0];
    const float* x_d   = (const float*)d_in[1];
    const float* x_s   = (const float*)d_in[2];
    const float* Win_p = (const float*)d_in[3];
    const float* bin_p = (const float*)d_in[4];
    const float* Win_d = (const float*)d_in[5];
    const float* bin_d = (const float*)d_in[6];
    const float* Win_s = (const float*)d_in[7];
    const float* bin_s = (const float*)d_in[8];
    const float* Wk    = (const float*)d_in[9];
    const float* bk    = (const float*)d_in[10];
    const float* Wq    = (const float*)d_in[11];
    const float* bq    = (const float*)d_in[12];
    const float* Wv    = (const float*)d_in[13];
    const float* bv    = (const float*)d_in[14];
    const float* Wa    = (const float*)d_in[15];
    const float* ba    = (const float*)d_in[16];
    const float* a_rel = (const float*)d_in[17];
    const float* m_rel = (const float*)d_in[18];
    const float* p_rel = (const float*)d_in[19];
    const float* skip  = (const float*)d_in[20];
    const int*   ei_pd = (const int*)d_in[21];
    const int*   ei_dp = (const int*)d_in[22];
    const int*   ei_ds = (const int*)d_in[23];
    const int*   ei_ps = (const int*)d_in[24];
    float* out = (float*)d_out;

    float *px, *pnum, *pden, *pWc, *pbc;
    __half *pq, *pkr, *pvr;
    cudaGetSymbolAddress((void**)&px,   g_x);
    cudaGetSymbolAddress((void**)&pq,   g_qh);
    cudaGetSymbolAddress((void**)&pkr,  g_kh);
    cudaGetSymbolAddress((void**)&pvr,  g_vh);
    cudaGetSymbolAddress((void**)&pnum, g_num);
    cudaGetSymbolAddress((void**)&pden, g_den);
    cudaGetSymbolAddress((void**)&pWc,  g_Wc);
    cudaGetSymbolAddress((void**)&pbc,  g_bc);

    const int BP = cdiv(N_P, 128);          // 782
    const int BD = cdiv(N_D, 128);          // 8
    const int BS = cdiv(N_S, 128);          // 40
    const int NG = BP + BD + BS;            // 830
    const size_t kr0 = 0, kr1 = N_P, kr2 = N_P + N_D, kr3 = N_P + 2*N_D;

    combine_weights<<<16, 256>>>(Wk, bk, Wv, bv, a_rel, m_rel, p_rel);

    // input projections (fp32)
    {
        ParamsI P;
        P.job[0] = { x_p, Win_p, bin_p, px,                        N_P, 0,     64 };
        P.job[1] = { x_d, Win_d, bin_d, px + (size_t)N_P*64,       N_D, BP,    128 };
        P.job[2] = { x_s, Win_s, bin_s, px + (size_t)(N_P+N_D)*64, N_S, BP+BD, 64 };
        gemm_input<<<NG, 128>>>(P);
    }

    for (int l = 0; l < 2; l++) {
        // Phase A: TF32 projections (fp16 out) + fused zeroing
        {
            ParamsA P;
            P.nblk_gemm = NG;
            JobA& j0 = P.job[0];
            j0.X = px; j0.M = N_P; j0.blk0 = 0; j0.nT = 5;
            j0.tl[0] = { Wq  + (size_t)(l*3+0)*4096, bq  + (size_t)(l*3+0)*64, pq };
            j0.tl[1] = { pWc + (size_t)(l*8+0)*4096, pbc + (size_t)(l*8+0)*64, pkr + kr0*64 };
            j0.tl[2] = { pWc + (size_t)(l*8+4)*4096, pbc + (size_t)(l*8+4)*64, pvr + kr0*64 };
            j0.tl[3] = { pWc + (size_t)(l*8+3)*4096, pbc + (size_t)(l*8+3)*64, pkr + kr3*64 };
            j0.tl[4] = { pWc + (size_t)(l*8+7)*4096, pbc + (size_t)(l*8+7)*64, pvr + kr3*64 };
            JobA& j1 = P.job[1];
            j1.X = px + (size_t)N_P*64; j1.M = N_D; j1.blk0 = BP; j1.nT = 5;
            j1.tl[0] = { Wq  + (size_t)(l*3+1)*4096, bq  + (size_t)(l*3+1)*64, pq + (size_t)N_P*64 };
            j1.tl[1] = { pWc + (size_t)(l*8+1)*4096, pbc + (size_t)(l*8+1)*64, pkr + kr1*64 };
            j1.tl[2] = { pWc + (size_t)(l*8+5)*4096, pbc + (size_t)(l*8+5)*64, pvr + kr1*64 };
            j1.tl[3] = { pWc + (size_t)(l*8+2)*4096, pbc + (size_t)(l*8+2)*64, pkr + kr2*64 };
            j1.tl[4] = { pWc + (size_t)(l*8+6)*4096, pbc + (size_t)(l*8+6)*64, pvr + kr2*64 };
            JobA& j2 = P.job[2];
            j2.X = px + (size_t)(N_P+N_D)*64; j2.M = N_S; j2.blk0 = BP+BD; j2.nT = 1;
            j2.tl[0] = { Wq + (size_t)(l*3+2)*4096, bq + (size_t)(l*3+2)*64, pq + (size_t)(N_P+N_D)*64 };
            j2.tl[1] = j2.tl[0]; j2.tl[2] = j2.tl[0]; j2.tl[3] = j2.tl[0]; j2.tl[4] = j2.tl[0];
            gemm_phaseA<<<NG + ZB, 128>>>(P);
        }

        // all relations, single launch
        edge_all<<<cdiv(ET * HD, 256), 256>>>(ei_pd, ei_dp, ei_ds, ei_ps);

        // epilogue (TF32)
        {
            float* Yb = (l == 0) ? px : out;
            ParamsE P;
            P.job[0] = { pnum + (size_t)N_D*64, pden + (size_t)N_D*4, nullptr, nullptr,
                         px, skip + l*3 + 0,
                         Wa + (size_t)(l*3+0)*4096, ba + (size_t)(l*3+0)*64, Yb,
                         N_P, 0 };
            P.job[1] = { pnum, pden, nullptr, nullptr,
                         px + (size_t)N_P*64, skip + l*3 + 1,
                         Wa + (size_t)(l*3+1)*4096, ba + (size_t)(l*3+1)*64, Yb + (size_t)N_P*64,
                         N_D, BP };
            P.job[2] = { pnum + (size_t)(N_D+N_P)*64, pden + (size_t)(N_D+N_P)*4,
                         pnum + (size_t)(N_D+N_P+N_S)*64, pden + (size_t)(N_D+N_P+N_S)*4,
                         px + (size_t)(N_P+N_D)*64, skip + l*3 + 2,
                         Wa + (size_t)(l*3+2)*4096, ba + (size_t)(l*3+2)*64, Yb + (size_t)(N_P+N_D)*64,
                         N_S, BP+BD };
            gemm_epilogue<<<NG, 128>>>(P);
        }
    }
    (void)in_sizes; (void)n_in; (void)out_size;
}

// round 13
// speedup vs baseline: 1.0460x; 1.0460x over previous
#include <cuda_runtime.h>
#include <cuda_fp16.h>
#include <math.h>

// ---------------- problem constants ----------------
#define N_P 100000
#define N_D 1000
#define N_S 5000
#define NT  (N_P + N_D + N_S)
#define CD  64
#define HD  4
#define E0 300000
#define E1 300000
#define E2 100000
#define E3 100000
#define ET (E0 + E1 + E2 + E3)
#define KREL_TOT (2*N_P + 2*N_D)
#define DSTN_TOT (N_D + N_P + 2*N_S)
#define XP 68   // Xs row pitch (floats)
#define WTP 68  // transposed-W row pitch (>=64 extent; 68%32=4 -> conflict-free reads)
#define ZB 222
#define DEN4 (DSTN_TOT)
#define NUM4 (DSTN_TOT * 16)
#define TOT4 (DEN4 + NUM4)

typedef unsigned long long u64;

// ---------------- device scratch ----------------
__device__ __align__(16) float  g_x[NT * CD];
__device__ __align__(16) __half g_qh[NT * CD];
__device__ __align__(16) __half g_kh[KREL_TOT * CD];
__device__ __align__(16) __half g_vh[KREL_TOT * CD];
__device__ __align__(16) float  g_den[DSTN_TOT * HD];
__device__ __align__(16) float  g_num[DSTN_TOT * CD];
__device__ __align__(16) float  g_Wc[16 * CD * CD];
__device__ __align__(16) float  g_bc[16 * CD];

// ---------------- helpers ----------------
__device__ __forceinline__ u64 pack2(float x) {
    u64 r; asm("mov.b64 %0, {%1, %1};" : "=l"(r) : "f"(x)); return r;
}
__device__ __forceinline__ u64 fma2(u64 a, u64 b, u64 c) {
    u64 d; asm("fma.rn.f32x2 %0, %1, %2, %3;" : "=l"(d) : "l"(a), "l"(b), "l"(c)); return d;
}
__device__ __forceinline__ float2 unpack2(u64 a) {
    float2 f; asm("mov.b64 {%0, %1}, %2;" : "=f"(f.x), "=f"(f.y) : "l"(a)); return f;
}
__device__ __forceinline__ float tf32r(float x) {   // round-to-nearest tf32
    unsigned r; asm("cvt.rna.tf32.f32 %0, %1;" : "=r"(r) : "f"(x));
    return __uint_as_float(r);
}

// ---------------- TF32 warp-MMA core: 128x64 @ 64x64 (accumulating) ----------------
__device__ __forceinline__ void tf32_mma(const float* Xs, const float* Wt,
                                         int rb, int gid, int tidg,
                                         float acc[2][8][4])
{
#pragma unroll
    for (int k0 = 0; k0 < 64; k0 += 8) {
        unsigned a[2][4];
#pragma unroll
        for (int mt = 0; mt < 2; mt++) {
            const float* xp = &Xs[(rb + mt * 16 + gid) * XP + k0 + tidg];
            a[mt][0] = __float_as_uint(xp[0]);
            a[mt][1] = __float_as_uint(xp[8 * XP]);
            a[mt][2] = __float_as_uint(xp[4]);
            a[mt][3] = __float_as_uint(xp[8 * XP + 4]);
        }
        unsigned b[8][2];
#pragma unroll
        for (int nt = 0; nt < 8; nt++) {
            const float* wp = &Wt[(nt * 8 + gid) * WTP + k0 + tidg];
            b[nt][0] = __float_as_uint(wp[0]);
            b[nt][1] = __float_as_uint(wp[4]);
        }
#pragma unroll
        for (int mt = 0; mt < 2; mt++)
#pragma unroll
            for (int nt = 0; nt < 8; nt++)
                asm volatile(
                    "mma.sync.aligned.m16n8k8.row.col.f32.tf32.tf32.f32 "
                    "{%0,%1,%2,%3}, {%4,%5,%6,%7}, {%8,%9}, {%0,%1,%2,%3};"
                    : "+f"(acc[mt][nt][0]), "+f"(acc[mt][nt][1]),
                      "+f"(acc[mt][nt][2]), "+f"(acc[mt][nt][3])
                    : "r"(a[mt][0]), "r"(a[mt][1]), "r"(a[mt][2]), "r"(a[mt][3]),
                      "r"(b[nt][0]), "r"(b[nt][1]));
    }
}

// ---------------- fp32 FFMA2 GEMM core (epilogue) ----------------
__device__ __forceinline__ void mma_core(const float* Xs, const float* Ws,
                                         int ty, int tx, u64 acc[8][4])
{
#pragma unroll 2
    for (int kk = 0; kk < 64; kk += 4) {
        float4 xv[8];
#pragma unroll
        for (int i = 0; i < 8; i++)
            xv[i] = *(const float4*)&Xs[(ty + i * 16) * XP + kk];
#pragma unroll
        for (int c = 0; c < 4; c++) {
            ulonglong2 wA = *(const ulonglong2*)&Ws[(kk + c) * 64 + tx * 8];
            ulonglong2 wB = *(const ulonglong2*)&Ws[(kk + c) * 64 + tx * 8 + 4];
            u64 w0 = wA.x, w1 = wA.y, w2 = wB.x, w3 = wB.y;
#pragma unroll
            for (int i = 0; i < 8; i++) {
                float xs = (c == 0) ? xv[i].x : (c == 1) ? xv[i].y
                         : (c == 2) ? xv[i].z : xv[i].w;
                u64 x2 = pack2(xs);
                acc[i][0] = fma2(x2, w0, acc[i][0]);
                acc[i][1] = fma2(x2, w1, acc[i][1]);
                acc[i][2] = fma2(x2, w2, acc[i][2]);
                acc[i][3] = fma2(x2, w3, acc[i][3]);
            }
        }
    }
}

// ---------------- combine weights ----------------
__global__ void combine_weights(const float* __restrict__ Wk, const float* __restrict__ bk,
                                const float* __restrict__ Wv, const float* __restrict__ bv,
                                const float* __restrict__ a_rel, const float* __restrict__ m_rel,
                                const float* __restrict__ p_rel)
{
    int blk = blockIdx.x;
    int l  = blk >> 3;
    int kv = (blk >> 2) & 1;
    int r  = blk & 3;
    const int st_tab[4] = {0, 1, 1, 0};
    int st = st_tab[r];

    const float* Wbase = (kv == 0 ? Wk : Wv) + (size_t)(l*3 + st) * CD * CD;
    const float* bbase = (kv == 0 ? bk : bv) + (size_t)(l*3 + st) * CD;
    const float* rel   = (kv == 0 ? a_rel : m_rel) + (size_t)(l*4 + r) * HD * 256;

    __shared__ float srel[HD * 256];
    __shared__ float sscale[HD];
    int t = threadIdx.x; // 256
    for (int i = t; i < HD*256; i += 256) srel[i] = rel[i];
    if (t < HD) sscale[t] = (kv == 0) ? p_rel[(l*4 + r) * HD + t] * 0.25f : 1.0f;
    __syncthreads();

    float* Wc = g_Wc + (size_t)blk * CD * CD;
    float* bc = g_bc + (size_t)blk * CD;

    int c = t >> 2, h = t & 3;
    float wrow[16];
#pragma unroll
    for (int d = 0; d < 16; d++) wrow[d] = Wbase[c*CD + h*16 + d];
    float sc = sscale[h];
#pragma unroll
    for (int e = 0; e < 16; e++) {
        float s = 0.f;
#pragma unroll
        for (int d = 0; d < 16; d++) s += wrow[d] * srel[h*256 + d*16 + e];
        Wc[c*CD + h*16 + e] = s * sc;
    }
    if (t < CD) {
        int hh = t >> 4, ee = t & 15;
        float s = 0.f;
#pragma unroll
        for (int d = 0; d < 16; d++) s += bbase[hh*16 + d] * srel[hh*256 + d*16 + ee];
        bc[t] = s * sscale[hh];
    }
}

// ---------------- job descriptors ----------------
struct TileW { const float* W; const float* b; __half* Y; };
struct JobA  { const float* X; int M; int blk0; int nT; TileW tl[5]; };
struct ParamsA { JobA job[3]; int nblk_gemm; };

struct JobE {
    const float* num0; const float* den0;
    const float* num1; const float* den1;
    const float* xold; const float* skipp;
    const float* W; const float* b; float* Y;
    int M; int blk0;
};
struct ParamsE { JobE job[3]; };

struct JobI { const float* X; const float* W; const float* b; float* Y; int M; int blk0; int K; };
struct ParamsI { JobI job[3]; };

// ---------------- Phase A: TF32 -> fp16 outputs + fused zeroing ----------------
__global__ void __launch_bounds__(128)
gemm_phaseA(ParamsA P)
{
    __shared__ float Xs[128 * XP];
    __shared__ float Wt[64 * WTP];
    int bx = blockIdx.x;
    int t = threadIdx.x;

    if (bx >= P.nblk_gemm) {
        int zb = bx - P.nblk_gemm;
        float4 z = make_float4(0.f, 0.f, 0.f, 0.f);
        float4* dp = (float4*)g_den;
        float4* np = (float4*)g_num;
        for (int i = zb * 128 + t; i < TOT4; i += ZB * 128) {
            if (i < DEN4) dp[i] = z;
            else          np[i - DEN4] = z;
        }
        return;
    }

    int j = (bx >= P.job[2].blk0) ? 2 : (bx >= P.job[1].blk0) ? 1 : 0;
    const JobA& J = P.job[j];
    int m0 = (bx - J.blk0) * 128;
    const int lane = t & 31, warp = t >> 5;
    const int gid = lane >> 2, tidg = lane & 3;
    const int rb = warp * 32;

#pragma unroll
    for (int i = 0; i < 16; i++) {
        int f4 = t + i * 128;
        int row = f4 >> 4, c4 = f4 & 15;
        float4 v = make_float4(0.f, 0.f, 0.f, 0.f);
        if (m0 + row < J.M) v = *(const float4*)&J.X[(size_t)(m0 + row) * 64 + c4 * 4];
        v.x = tf32r(v.x); v.y = tf32r(v.y); v.z = tf32r(v.z); v.w = tf32r(v.w);
        *(float4*)&Xs[row * XP + c4 * 4] = v;
    }

    for (int ti = 0; ti < J.nT; ti++) {
        __syncthreads();
        const float* __restrict__ W = J.tl[ti].W;
#pragma unroll 8
        for (int i = 0; i < 32; i++) {
            int idx = t + i * 128;
            int k = idx >> 6, n = idx & 63;
            Wt[n * WTP + k] = tf32r(W[idx]);
        }
        __syncthreads();

        float acc[2][8][4];
#pragma unroll
        for (int mt = 0; mt < 2; mt++)
#pragma unroll
            for (int nt = 0; nt < 8; nt++)
#pragma unroll
                for (int r = 0; r < 4; r++) acc[mt][nt][r] = 0.f;

        tf32_mma(Xs, Wt, rb, gid, tidg, acc);

        const float* bias = J.tl[ti].b;
        __half* Y = J.tl[ti].Y;
        float bb[16];
#pragma unroll
        for (int nt = 0; nt < 8; nt++) {
            bb[2*nt]     = bias[nt * 8 + tidg * 2];
            bb[2*nt + 1] = bias[nt * 8 + tidg * 2 + 1];
        }
#pragma unroll
        for (int mt = 0; mt < 2; mt++) {
#pragma unroll
            for (int rr = 0; rr < 2; rr++) {
                int row = m0 + rb + mt * 16 + rr * 8 + gid;
                if (row < J.M) {
#pragma unroll
                    for (int nt = 0; nt < 8; nt++) {
                        float v0 = acc[mt][nt][2*rr]     + bb[2*nt];
                        float v1 = acc[mt][nt][2*rr + 1] + bb[2*nt + 1];
                        *(__half2*)&Y[(size_t)row * 64 + nt * 8 + tidg * 2] =
                            __floats2half2_rn(v0, v1);
                    }
                }
            }
        }
    }
}

// ---------------- Epilogue (128 thr, fp32 FFMA2 — round-11 proven) ----------------
__global__ void __launch_bounds__(128)
gemm_epilogue(ParamsE P)
{
    __shared__ float Xs[128 * XP];
    __shared__ __align__(16) float Ws[64 * 64];
    int bx = blockIdx.x;
    int j = (bx >= P.job[2].blk0) ? 2 : (bx >= P.job[1].blk0) ? 1 : 0;
    const JobE& J = P.job[j];
    int m0 = (bx - J.blk0) * 128;
    int t = threadIdx.x;
    const int ty = t >> 3, tx = t & 7;

#pragma unroll
    for (int i = 0; i < 64; i++) {
        int idx = t + i * 128;
        int row = idx >> 6, cc = idx & 63;
        float val = 0.f;
        int n = m0 + row;
        if (n < J.M) {
            int h = cc >> 4;
            val = J.num0[(size_t)n * 64 + cc] / (J.den0[(size_t)n * 4 + h] + 1e-16f);
            if (J.num1)
                val += J.num1[(size_t)n * 64 + cc] / (J.den1[(size_t)n * 4 + h] + 1e-16f);
            val = 0.5f * val * (1.0f + erff(val * 0.70710678118654752f));
        }
        Xs[row * XP + cc] = val;
    }
#pragma unroll
    for (int i = 0; i < 8; i++) {
        int f4 = (t + i * 128) * 4;
        *(float4*)&Ws[f4] = *(const float4*)&J.W[f4];
    }
    __syncthreads();

    u64 acc[8][4];
#pragma unroll
    for (int i = 0; i < 8; i++)
#pragma unroll
        for (int k = 0; k < 4; k++) acc[i][k] = 0ull;

    mma_core(Xs, Ws, ty, tx, acc);

    float bb[8];
#pragma unroll
    for (int q = 0; q < 8; q++) bb[q] = J.b[tx * 8 + q];
    float s = 1.0f / (1.0f + expf(-J.skipp[0]));
    float om = 1.0f - s;

#pragma unroll
    for (int i = 0; i < 8; i++) {
        int row = m0 + ty + i * 16;
        if (row < J.M) {
            float o[8];
#pragma unroll
            for (int k = 0; k < 4; k++) {
                float2 p = unpack2(acc[i][k]);
                o[2*k] = p.x + bb[2*k]; o[2*k+1] = p.y + bb[2*k+1];
            }
            float4 x0 = *(const float4*)&J.xold[(size_t)row * 64 + tx * 8];
            float4 x1 = *(const float4*)&J.xold[(size_t)row * 64 + tx * 8 + 4];
            o[0] = s*o[0] + om*x0.x; o[1] = s*o[1] + om*x0.y;
            o[2] = s*o[2] + om*x0.z; o[3] = s*o[3] + om*x0.w;
            o[4] = s*o[4] + om*x1.x; o[5] = s*o[5] + om*x1.y;
            o[6] = s*o[6] + om*x1.z; o[7] = s*o[7] + om*x1.w;
            *(float4*)&J.Y[(size_t)row * 64 + tx * 8]     = make_float4(o[0], o[1], o[2], o[3]);
            *(float4*)&J.Y[(size_t)row * 64 + tx * 8 + 4] = make_float4(o[4], o[5], o[6], o[7]);
        }
    }
}

// ---------------- Input projections: TF32 (runtime K, fp32 out) ----------------
__global__ void __launch_bounds__(128)
gemm_input(ParamsI P)
{
    __shared__ float Xs[128 * XP];
    __shared__ float Wt[64 * WTP];
    int bx = blockIdx.x;
    int j = (bx >= P.job[2].blk0) ? 2 : (bx >= P.job[1].blk0) ? 1 : 0;
    const JobI& J = P.job[j];
    int m0 = (bx - J.blk0) * 128;
    int t = threadIdx.x;
    const int lane = t & 31, warp = t >> 5;
    const int gid = lane >> 2, tidg = lane & 3;
    const int rb = warp * 32;
    const int K = J.K;

    float acc[2][8][4];
#pragma unroll
    for (int mt = 0; mt < 2; mt++)
#pragma unroll
        for (int nt = 0; nt < 8; nt++)
#pragma unroll
            for (int r = 0; r < 4; r++) acc[mt][nt][r] = 0.f;

    for (int k0 = 0; k0 < K; k0 += 64) {
        __syncthreads();
#pragma unroll
        for (int i = 0; i < 16; i++) {
            int f4 = t + i * 128;
            int row = f4 >> 4, c4 = f4 & 15;
            float4 v = make_float4(0.f, 0.f, 0.f, 0.f);
            if (m0 + row < J.M) v = *(const float4*)&J.X[(size_t)(m0 + row) * K + k0 + c4 * 4];
            v.x = tf32r(v.x); v.y = tf32r(v.y); v.z = tf32r(v.z); v.w = tf32r(v.w);
            *(float4*)&Xs[row * XP + c4 * 4] = v;
        }
#pragma unroll 8
        for (int i = 0; i < 32; i++) {
            int idx = t + i * 128;
            int k = idx >> 6, n = idx & 63;
            Wt[n * WTP + k] = tf32r(J.W[(size_t)(k0 + k) * 64 + n]);
        }
        __syncthreads();
        tf32_mma(Xs, Wt, rb, gid, tidg, acc);
    }

    float bb[16];
#pragma unroll
    for (int nt = 0; nt < 8; nt++) {
        bb[2*nt]     = J.b[nt * 8 + tidg * 2];
        bb[2*nt + 1] = J.b[nt * 8 + tidg * 2 + 1];
    }
#pragma unroll
    for (int mt = 0; mt < 2; mt++) {
#pragma unroll
        for (int rr = 0; rr < 2; rr++) {
            int row = m0 + rb + mt * 16 + rr * 8 + gid;
            if (row < J.M) {
#pragma unroll
                for (int nt = 0; nt < 8; nt++) {
                    float v0 = acc[mt][nt][2*rr]     + bb[2*nt];
                    float v1 = acc[mt][nt][2*rr + 1] + bb[2*nt + 1];
                    *(float2*)&J.Y[(size_t)row * 64 + nt * 8 + tidg * 2] = make_float2(v0, v1);
                }
            }
        }
    }
}

// ---------------- merged single-pass edge kernel (fp16 gathers, fp32 math) ----------------
__global__ void edge_all(const int* __restrict__ ei0, const int* __restrict__ ei1,
                         const int* __restrict__ ei2, const int* __restrict__ ei3)
{
    int gid = blockIdx.x * blockDim.x + threadIdx.x;
    if (gid >= ET * HD) return;
    int e = gid >> 2, h = gid & 3;

    const int* ei; int er, E, kvoff, qoff, dnoff;
    if (e < E0)                 { ei = ei0; er = e;            E = E0; kvoff = 0;           qoff = N_P;     dnoff = 0; }
    else if (e < E0+E1)         { ei = ei1; er = e - E0;       E = E1; kvoff = N_P;         qoff = 0;       dnoff = N_D; }
    else if (e < E0+E1+E2)      { ei = ei2; er = e - (E0+E1);  E = E2; kvoff = N_P+N_D;     qoff = N_P+N_D; dnoff = N_D+N_P; }
    else                        { ei = ei3; er = e-(E0+E1+E2); E = E3; kvoff = N_P+2*N_D;   qoff = N_P+N_D; dnoff = N_D+N_P+N_S; }

    int src = __ldg(&ei[er]);
    int dst = __ldg(&ei[E + er]);

    const uint4* qp = (const uint4*)&g_qh[(size_t)(qoff + dst) * 64 + h * 16];
    const uint4* kp = (const uint4*)&g_kh[(size_t)(kvoff + src) * 64 + h * 16];
    const uint4* vp = (const uint4*)&g_vh[(size_t)(kvoff + src) * 64 + h * 16];

    __half2 qv[8], kv[8], vv[8];
    *(uint4*)&qv[0] = qp[0]; *(uint4*)&qv[4] = qp[1];
    *(uint4*)&kv[0] = kp[0]; *(uint4*)&kv[4] = kp[1];
    *(uint4*)&vv[0] = vp[0]; *(uint4*)&vv[4] = vp[1];

    float a = 0.f;
#pragma unroll
    for (int jj = 0; jj < 8; jj++) {
        float2 qf = __half22float2(qv[jj]);
        float2 kf = __half22float2(kv[jj]);
        a += qf.x * kf.x + qf.y * kf.y;
    }
    float w = __expf(fminf(a, 60.f));
    atomicAdd(&g_den[(size_t)(dnoff + dst) * 4 + h], w);

    float4* np = (float4*)&g_num[(size_t)(dnoff + dst) * 64 + h * 16];
#pragma unroll
    for (int jj = 0; jj < 4; jj++) {
        float2 v0 = __half22float2(vv[2*jj]);
        float2 v1 = __half22float2(vv[2*jj + 1]);
        atomicAdd(&np[jj], make_float4(v0.x * w, v0.y * w, v1.x * w, v1.y * w));
    }
}

// ---------------- host orchestration ----------------
static inline int cdiv(int a, int b) { return (a + b - 1) / b; }

extern "C" void kernel_launch(void* const* d_in, const int* in_sizes, int n_in,
                              void* d_out, int out_size)
{
    const float* x_p   = (const float*)d_in[0];
    const float* x_d   = (const float*)d_in[1];
    const float* x_s   = (const float*)d_in[2];
    const float* Win_p = (const float*)d_in[3];
    const float* bin_p = (const float*)d_in[4];
    const float* Win_d = (const float*)d_in[5];
    const float* bin_d = (const float*)d_in[6];
    const float* Win_s = (const float*)d_in[7];
    const float* bin_s = (const float*)d_in[8];
    const float* Wk    = (const float*)d_in[9];
    const float* bk    = (const float*)d_in[10];
    const float* Wq    = (const float*)d_in[11];
    const float* bq    = (const float*)d_in[12];
    const float* Wv    = (const float*)d_in[13];
    const float* bv    = (const float*)d_in[14];
    const float* Wa    = (const float*)d_in[15];
    const float* ba    = (const float*)d_in[16];
    const float* a_rel = (const float*)d_in[17];
    const float* m_rel = (const float*)d_in[18];
    const float* p_rel = (const float*)d_in[19];
    const float* skip  = (const float*)d_in[20];
    const int*   ei_pd = (const int*)d_in[21];
    const int*   ei_dp = (const int*)d_in[22];
    const int*   ei_ds = (const int*)d_in[23];
    const int*   ei_ps = (const int*)d_in[24];
    float* out = (float*)d_out;

    float *px, *pnum, *pden, *pWc, *pbc;
    __half *pq, *pkr, *pvr;
    cudaGetSymbolAddress((void**)&px,   g_x);
    cudaGetSymbolAddress((void**)&pq,   g_qh);
    cudaGetSymbolAddress((void**)&pkr,  g_kh);
    cudaGetSymbolAddress((void**)&pvr,  g_vh);
    cudaGetSymbolAddress((void**)&pnum, g_num);
    cudaGetSymbolAddress((void**)&pden, g_den);
    cudaGetSymbolAddress((void**)&pWc,  g_Wc);
    cudaGetSymbolAddress((void**)&pbc,  g_bc);

    const int BP = cdiv(N_P, 128);          // 782
    const int BD = cdiv(N_D, 128);          // 8
    const int BS = cdiv(N_S, 128);          // 40
    const int NG = BP + BD + BS;            // 830
    const size_t kr0 = 0, kr1 = N_P, kr2 = N_P + N_D, kr3 = N_P + 2*N_D;

    combine_weights<<<16, 256>>>(Wk, bk, Wv, bv, a_rel, m_rel, p_rel);

    // input projections (TF32)
    {
        ParamsI P;
        P.job[0] = { x_p, Win_p, bin_p, px,                        N_P, 0,     64 };
        P.job[1] = { x_d, Win_d, bin_d, px + (size_t)N_P*64,       N_D, BP,    128 };
        P.job[2] = { x_s, Win_s, bin_s, px + (size_t)(N_P+N_D)*64, N_S, BP+BD, 64 };
        gemm_input<<<NG, 128>>>(P);
    }

    for (int l = 0; l < 2; l++) {
        // Phase A: TF32 projections (fp16 out) + fused zeroing
        {
            ParamsA P;
            P.nblk_gemm = NG;
            JobA& j0 = P.job[0];
            j0.X = px; j0.M = N_P; j0.blk0 = 0; j0.nT = 5;
            j0.tl[0] = { Wq  + (size_t)(l*3+0)*4096, bq  + (size_t)(l*3+0)*64, pq };
            j0.tl[1] = { pWc + (size_t)(l*8+0)*4096, pbc + (size_t)(l*8+0)*64, pkr + kr0*64 };
            j0.tl[2] = { pWc + (size_t)(l*8+4)*4096, pbc + (size_t)(l*8+4)*64, pvr + kr0*64 };
            j0.tl[3] = { pWc + (size_t)(l*8+3)*4096, pbc + (size_t)(l*8+3)*64, pkr + kr3*64 };
            j0.tl[4] = { pWc + (size_t)(l*8+7)*4096, pbc + (size_t)(l*8+7)*64, pvr + kr3*64 };
            JobA& j1 = P.job[1];
            j1.X = px + (size_t)N_P*64; j1.M = N_D; j1.blk0 = BP; j1.nT = 5;
            j1.tl[0] = { Wq  + (size_t)(l*3+1)*4096, bq  + (size_t)(l*3+1)*64, pq + (size_t)N_P*64 };
            j1.tl[1] = { pWc + (size_t)(l*8+1)*4096, pbc + (size_t)(l*8+1)*64, pkr + kr1*64 };
            j1.tl[2] = { pWc + (size_t)(l*8+5)*4096, pbc + (size_t)(l*8+5)*64, pvr + kr1*64 };
            j1.tl[3] = { pWc + (size_t)(l*8+2)*4096, pbc + (size_t)(l*8+2)*64, pkr + kr2*64 };
            j1.tl[4] = { pWc + (size_t)(l*8+6)*4096, pbc + (size_t)(l*8+6)*64, pvr + kr2*64 };
            JobA& j2 = P.job[2];
            j2.X = px + (size_t)(N_P+N_D)*64; j2.M = N_S; j2.blk0 = BP+BD; j2.nT = 1;
            j2.tl[0] = { Wq + (size_t)(l*3+2)*4096, bq + (size_t)(l*3+2)*64, pq + (size_t)(N_P+N_D)*64 };
            j2.tl[1] = j2.tl[0]; j2.tl[2] = j2.tl[0]; j2.tl[3] = j2.tl[0]; j2.tl[4] = j2.tl[0];
            gemm_phaseA<<<NG + ZB, 128>>>(P);
        }

        // all relations, single launch
        edge_all<<<cdiv(ET * HD, 256), 256>>>(ei_pd, ei_dp, ei_ds, ei_ps);

        // epilogue (fp32 FFMA2)
        {
            float* Yb = (l == 0) ? px : out;
            ParamsE P;
            P.job[0] = { pnum + (size_t)N_D*64, pden + (size_t)N_D*4, nullptr, nullptr,
                         px, skip + l*3 + 0,
                         Wa + (size_t)(l*3+0)*4096, ba + (size_t)(l*3+0)*64, Yb,
                         N_P, 0 };
            P.job[1] = { pnum, pden, nullptr, nullptr,
                         px + (size_t)N_P*64, skip + l*3 + 1,
                         Wa + (size_t)(l*3+1)*4096, ba + (size_t)(l*3+1)*64, Yb + (size_t)N_P*64,
                         N_D, BP };
            P.job[2] = { pnum + (size_t)(N_D+N_P)*64, pden + (size_t)(N_D+N_P)*4,
                         pnum + (size_t)(N_D+N_P+N_S)*64, pden + (size_t)(N_D+N_P+N_S)*4,
                         px + (size_t)(N_P+N_D)*64, skip + l*3 + 2,
                         Wa + (size_t)(l*3+2)*4096, ba + (size_t)(l*3+2)*64, Yb + (size_t)(N_P+N_D)*64,
                         N_S, BP+BD };
            gemm_epilogue<<<NG, 128>>>(P);
        }
    }
    (void)in_sizes; (void)n_in; (void)out_size;
}

// round 14
// speedup vs baseline: 1.3889x; 1.3278x over previous
#include <cuda_runtime.h>
#include <cuda_fp16.h>
#include <math.h>

// ---------------- problem constants ----------------
#define N_P 100000
#define N_D 1000
#define N_S 5000
#define NT  (N_P + N_D + N_S)
#define CD  64
#define HD  4
#define E0 300000
#define E1 300000
#define E2 100000
#define E3 100000
#define ET (E0 + E1 + E2 + E3)
#define KREL_TOT (2*N_P + 2*N_D)
#define DSTN_TOT (N_D + N_P + 2*N_S)
#define XP 68   // Xs row pitch (floats)
#define WTP 68  // transposed-W row pitch (>=64 extent; 68%32=4 -> conflict-free reads)
#define ZB 222
#define DEN4 (DSTN_TOT)
#define NUM4 (DSTN_TOT * 16)
#define TOT4 (DEN4 + NUM4)

typedef unsigned long long u64;

// ---------------- device scratch ----------------
__device__ __align__(16) float  g_x[NT * CD];
__device__ __align__(16) __half g_qh[NT * CD];
__device__ __align__(16) __half g_kh[KREL_TOT * CD];
__device__ __align__(16) __half g_vh[KREL_TOT * CD];
__device__ __align__(16) float  g_den[DSTN_TOT * HD];
__device__ __align__(16) float  g_num[DSTN_TOT * CD];
__device__ __align__(16) float  g_Wc[16 * CD * CD];
__device__ __align__(16) float  g_bc[16 * CD];

// ---------------- helpers ----------------
__device__ __forceinline__ u64 pack2(float x) {
    u64 r; asm("mov.b64 %0, {%1, %1};" : "=l"(r) : "f"(x)); return r;
}
__device__ __forceinline__ u64 fma2(u64 a, u64 b, u64 c) {
    u64 d; asm("fma.rn.f32x2 %0, %1, %2, %3;" : "=l"(d) : "l"(a), "l"(b), "l"(c)); return d;
}
__device__ __forceinline__ float2 unpack2(u64 a) {
    float2 f; asm("mov.b64 {%0, %1}, %2;" : "=f"(f.x), "=f"(f.y) : "l"(a)); return f;
}
__device__ __forceinline__ float tf32r(float x) {   // round-to-nearest tf32
    unsigned r; asm("cvt.rna.tf32.f32 %0, %1;" : "=r"(r) : "f"(x));
    return __uint_as_float(r);
}
__device__ __forceinline__ float gelu_exact(float x) {
    return 0.5f * x * (1.0f + erff(x * 0.70710678118654752f));
}

// ---------------- TF32 warp-MMA core: 128x64 @ 64x64 (accumulating) ----------------
__device__ __forceinline__ void tf32_mma(const float* Xs, const float* Wt,
                                         int rb, int gid, int tidg,
                                         float acc[2][8][4])
{
#pragma unroll
    for (int k0 = 0; k0 < 64; k0 += 8) {
        unsigned a[2][4];
#pragma unroll
        for (int mt = 0; mt < 2; mt++) {
            const float* xp = &Xs[(rb + mt * 16 + gid) * XP + k0 + tidg];
            a[mt][0] = __float_as_uint(xp[0]);
            a[mt][1] = __float_as_uint(xp[8 * XP]);
            a[mt][2] = __float_as_uint(xp[4]);
            a[mt][3] = __float_as_uint(xp[8 * XP + 4]);
        }
        unsigned b[8][2];
#pragma unroll
        for (int nt = 0; nt < 8; nt++) {
            const float* wp = &Wt[(nt * 8 + gid) * WTP + k0 + tidg];
            b[nt][0] = __float_as_uint(wp[0]);
            b[nt][1] = __float_as_uint(wp[4]);
        }
#pragma unroll
        for (int mt = 0; mt < 2; mt++)
#pragma unroll
            for (int nt = 0; nt < 8; nt++)
                asm volatile(
                    "mma.sync.aligned.m16n8k8.row.col.f32.tf32.tf32.f32 "
                    "{%0,%1,%2,%3}, {%4,%5,%6,%7}, {%8,%9}, {%0,%1,%2,%3};"
                    : "+f"(acc[mt][nt][0]), "+f"(acc[mt][nt][1]),
                      "+f"(acc[mt][nt][2]), "+f"(acc[mt][nt][3])
                    : "r"(a[mt][0]), "r"(a[mt][1]), "r"(a[mt][2]), "r"(a[mt][3]),
                      "r"(b[nt][0]), "r"(b[nt][1]));
    }
}

// ---------------- fp32 FFMA2 GEMM core (epilogue) ----------------
__device__ __forceinline__ void mma_core(const float* Xs, const float* Ws,
                                         int ty, int tx, u64 acc[8][4])
{
#pragma unroll 2
    for (int kk = 0; kk < 64; kk += 4) {
        float4 xv[8];
#pragma unroll
        for (int i = 0; i < 8; i++)
            xv[i] = *(const float4*)&Xs[(ty + i * 16) * XP + kk];
#pragma unroll
        for (int c = 0; c < 4; c++) {
            ulonglong2 wA = *(const ulonglong2*)&Ws[(kk + c) * 64 + tx * 8];
            ulonglong2 wB = *(const ulonglong2*)&Ws[(kk + c) * 64 + tx * 8 + 4];
            u64 w0 = wA.x, w1 = wA.y, w2 = wB.x, w3 = wB.y;
#pragma unroll
            for (int i = 0; i < 8; i++) {
                float xs = (c == 0) ? xv[i].x : (c == 1) ? xv[i].y
                         : (c == 2) ? xv[i].z : xv[i].w;
                u64 x2 = pack2(xs);
                acc[i][0] = fma2(x2, w0, acc[i][0]);
                acc[i][1] = fma2(x2, w1, acc[i][1]);
                acc[i][2] = fma2(x2, w2, acc[i][2]);
                acc[i][3] = fma2(x2, w3, acc[i][3]);
            }
        }
    }
}

// ---------------- combine weights ----------------
__global__ void combine_weights(const float* __restrict__ Wk, const float* __restrict__ bk,
                                const float* __restrict__ Wv, const float* __restrict__ bv,
                                const float* __restrict__ a_rel, const float* __restrict__ m_rel,
                                const float* __restrict__ p_rel)
{
    int blk = blockIdx.x;
    int l  = blk >> 3;
    int kv = (blk >> 2) & 1;
    int r  = blk & 3;
    const int st_tab[4] = {0, 1, 1, 0};
    int st = st_tab[r];

    const float* Wbase = (kv == 0 ? Wk : Wv) + (size_t)(l*3 + st) * CD * CD;
    const float* bbase = (kv == 0 ? bk : bv) + (size_t)(l*3 + st) * CD;
    const float* rel   = (kv == 0 ? a_rel : m_rel) + (size_t)(l*4 + r) * HD * 256;

    __shared__ float srel[HD * 256];
    __shared__ float sscale[HD];
    int t = threadIdx.x; // 256
    for (int i = t; i < HD*256; i += 256) srel[i] = rel[i];
    if (t < HD) sscale[t] = (kv == 0) ? p_rel[(l*4 + r) * HD + t] * 0.25f : 1.0f;
    __syncthreads();

    float* Wc = g_Wc + (size_t)blk * CD * CD;
    float* bc = g_bc + (size_t)blk * CD;

    int c = t >> 2, h = t & 3;
    float wrow[16];
#pragma unroll
    for (int d = 0; d < 16; d++) wrow[d] = Wbase[c*CD + h*16 + d];
    float sc = sscale[h];
#pragma unroll
    for (int e = 0; e < 16; e++) {
        float s = 0.f;
#pragma unroll
        for (int d = 0; d < 16; d++) s += wrow[d] * srel[h*256 + d*16 + e];
        Wc[c*CD + h*16 + e] = s * sc;
    }
    if (t < CD) {
        int hh = t >> 4, ee = t & 15;
        float s = 0.f;
#pragma unroll
        for (int d = 0; d < 16; d++) s += bbase[hh*16 + d] * srel[hh*256 + d*16 + ee];
        bc[t] = s * sscale[hh];
    }
}

// ---------------- job descriptors ----------------
struct TileW { const float* W; const float* b; __half* Y; };
struct JobA  { const float* X; int M; int blk0; int nT; TileW tl[5]; };
struct ParamsA { JobA job[3]; int nblk_gemm; };

struct JobE {
    const float* num0; const float* den0;
    const float* num1; const float* den1;
    const float* xold; const float* skipp;
    const float* W; const float* b; float* Y;
    int M; int blk0;
};
struct ParamsE { JobE job[3]; };

struct JobI { const float* X; const float* W; const float* b; float* Y; int M; int blk0; int K; };
struct ParamsI { JobI job[3]; };

// ---------------- Phase A: TF32 -> fp16 outputs + fused zeroing ----------------
__global__ void __launch_bounds__(128)
gemm_phaseA(ParamsA P)
{
    __shared__ float Xs[128 * XP];
    __shared__ float Wt[64 * WTP];
    int bx = blockIdx.x;
    int t = threadIdx.x;

    if (bx >= P.nblk_gemm) {
        int zb = bx - P.nblk_gemm;
        float4 z = make_float4(0.f, 0.f, 0.f, 0.f);
        float4* dp = (float4*)g_den;
        float4* np = (float4*)g_num;
        for (int i = zb * 128 + t; i < TOT4; i += ZB * 128) {
            if (i < DEN4) dp[i] = z;
            else          np[i - DEN4] = z;
        }
        return;
    }

    int j = (bx >= P.job[2].blk0) ? 2 : (bx >= P.job[1].blk0) ? 1 : 0;
    const JobA& J = P.job[j];
    int m0 = (bx - J.blk0) * 128;
    const int lane = t & 31, warp = t >> 5;
    const int gid = lane >> 2, tidg = lane & 3;
    const int rb = warp * 32;

#pragma unroll
    for (int i = 0; i < 16; i++) {
        int f4 = t + i * 128;
        int row = f4 >> 4, c4 = f4 & 15;
        float4 v = make_float4(0.f, 0.f, 0.f, 0.f);
        if (m0 + row < J.M) v = *(const float4*)&J.X[(size_t)(m0 + row) * 64 + c4 * 4];
        v.x = tf32r(v.x); v.y = tf32r(v.y); v.z = tf32r(v.z); v.w = tf32r(v.w);
        *(float4*)&Xs[row * XP + c4 * 4] = v;
    }

    for (int ti = 0; ti < J.nT; ti++) {
        __syncthreads();
        const float* __restrict__ W = J.tl[ti].W;
#pragma unroll 8
        for (int i = 0; i < 32; i++) {
            int idx = t + i * 128;
            int k = idx >> 6, n = idx & 63;
            Wt[n * WTP + k] = tf32r(W[idx]);
        }
        __syncthreads();

        float acc[2][8][4];
#pragma unroll
        for (int mt = 0; mt < 2; mt++)
#pragma unroll
            for (int nt = 0; nt < 8; nt++)
#pragma unroll
                for (int r = 0; r < 4; r++) acc[mt][nt][r] = 0.f;

        tf32_mma(Xs, Wt, rb, gid, tidg, acc);

        const float* bias = J.tl[ti].b;
        __half* Y = J.tl[ti].Y;
        float bb[16];
#pragma unroll
        for (int nt = 0; nt < 8; nt++) {
            bb[2*nt]     = bias[nt * 8 + tidg * 2];
            bb[2*nt + 1] = bias[nt * 8 + tidg * 2 + 1];
        }
#pragma unroll
        for (int mt = 0; mt < 2; mt++) {
#pragma unroll
            for (int rr = 0; rr < 2; rr++) {
                int row = m0 + rb + mt * 16 + rr * 8 + gid;
                if (row < J.M) {
#pragma unroll
                    for (int nt = 0; nt < 8; nt++) {
                        float v0 = acc[mt][nt][2*rr]     + bb[2*nt];
                        float v1 = acc[mt][nt][2*rr + 1] + bb[2*nt + 1];
                        *(__half2*)&Y[(size_t)row * 64 + nt * 8 + tidg * 2] =
                            __floats2half2_rn(v0, v1);
                    }
                }
            }
        }
    }
}

// ---------------- Epilogue (128 thr, fp32 FFMA2; hoisted reciprocals + float4 fill) ----------------
__global__ void __launch_bounds__(128)
gemm_epilogue(ParamsE P)
{
    __shared__ float Xs[128 * XP];
    __shared__ __align__(16) float Ws[64 * 64];
    __shared__ float sinv[128 * 8];   // [row][0..3]=inv den0, [row][4..7]=inv den1
    int bx = blockIdx.x;
    int j = (bx >= P.job[2].blk0) ? 2 : (bx >= P.job[1].blk0) ? 1 : 0;
    const JobE& J = P.job[j];
    int m0 = (bx - J.blk0) * 128;
    int t = threadIdx.x;
    const int ty = t >> 3, tx = t & 7;

    // pass 1: reciprocals, one per (row, head)
#pragma unroll
    for (int i = 0; i < 4; i++) {
        int idx = t + i * 128;        // 0..511
        int row = idx >> 2, h = idx & 3;
        int n = m0 + row;
        float v0 = 0.f, v1 = 0.f;
        if (n < J.M) {
            v0 = 1.0f / (J.den0[(size_t)n * 4 + h] + 1e-16f);
            if (J.den1) v1 = 1.0f / (J.den1[(size_t)n * 4 + h] + 1e-16f);
        }
        sinv[row * 8 + h]     = v0;
        sinv[row * 8 + 4 + h] = v1;
    }
    __syncthreads();

    // pass 2: vectorized gelu(num*inv) fill
#pragma unroll
    for (int i = 0; i < 16; i++) {
        int idx = t + i * 128;        // 0..2047 float4 slots
        int row = idx >> 4, c4 = idx & 15;
        int n = m0 + row;
        float4 v = make_float4(0.f, 0.f, 0.f, 0.f);
        if (n < J.M) {
            int h = c4 >> 2;          // constant head within a float4
            float inv0 = sinv[row * 8 + h];
            float4 a = *(const float4*)&J.num0[(size_t)n * 64 + c4 * 4];
            v.x = a.x * inv0; v.y = a.y * inv0; v.z = a.z * inv0; v.w = a.w * inv0;
            if (J.num1) {
                float inv1 = sinv[row * 8 + 4 + h];
                float4 b = *(const float4*)&J.num1[(size_t)n * 64 + c4 * 4];
                v.x += b.x * inv1; v.y += b.y * inv1;
                v.z += b.z * inv1; v.w += b.w * inv1;
            }
            v.x = gelu_exact(v.x); v.y = gelu_exact(v.y);
            v.z = gelu_exact(v.z); v.w = gelu_exact(v.w);
        }
        *(float4*)&Xs[row * XP + c4 * 4] = v;
    }
#pragma unroll
    for (int i = 0; i < 8; i++) {
        int f4 = (t + i * 128) * 4;
        *(float4*)&Ws[f4] = *(const float4*)&J.W[f4];
    }
    __syncthreads();

    u64 acc[8][4];
#pragma unroll
    for (int i = 0; i < 8; i++)
#pragma unroll
        for (int k = 0; k < 4; k++) acc[i][k] = 0ull;

    mma_core(Xs, Ws, ty, tx, acc);

    float bb[8];
#pragma unroll
    for (int q = 0; q < 8; q++) bb[q] = J.b[tx * 8 + q];
    float s = 1.0f / (1.0f + expf(-J.skipp[0]));
    float om = 1.0f - s;

#pragma unroll
    for (int i = 0; i < 8; i++) {
        int row = m0 + ty + i * 16;
        if (row < J.M) {
            float o[8];
#pragma unroll
            for (int k = 0; k < 4; k++) {
                float2 p = unpack2(acc[i][k]);
                o[2*k] = p.x + bb[2*k]; o[2*k+1] = p.y + bb[2*k+1];
            }
            float4 x0 = *(const float4*)&J.xold[(size_t)row * 64 + tx * 8];
            float4 x1 = *(const float4*)&J.xold[(size_t)row * 64 + tx * 8 + 4];
            o[0] = s*o[0] + om*x0.x; o[1] = s*o[1] + om*x0.y;
            o[2] = s*o[2] + om*x0.z; o[3] = s*o[3] + om*x0.w;
            o[4] = s*o[4] + om*x1.x; o[5] = s*o[5] + om*x1.y;
            o[6] = s*o[6] + om*x1.z; o[7] = s*o[7] + om*x1.w;
            *(float4*)&J.Y[(size_t)row * 64 + tx * 8]     = make_float4(o[0], o[1], o[2], o[3]);
            *(float4*)&J.Y[(size_t)row * 64 + tx * 8 + 4] = make_float4(o[4], o[5], o[6], o[7]);
        }
    }
}

// ---------------- Input projections: TF32 (runtime K, fp32 out) ----------------
__global__ void __launch_bounds__(128)
gemm_input(ParamsI P)
{
    __shared__ float Xs[128 * XP];
    __shared__ float Wt[64 * WTP];
    int bx = blockIdx.x;
    int j = (bx >= P.job[2].blk0) ? 2 : (bx >= P.job[1].blk0) ? 1 : 0;
    const JobI& J = P.job[j];
    int m0 = (bx - J.blk0) * 128;
    int t = threadIdx.x;
    const int lane = t & 31, warp = t >> 5;
    const int gid = lane >> 2, tidg = lane & 3;
    const int rb = warp * 32;
    const int K = J.K;

    float acc[2][8][4];
#pragma unroll
    for (int mt = 0; mt < 2; mt++)
#pragma unroll
        for (int nt = 0; nt < 8; nt++)
#pragma unroll
            for (int r = 0; r < 4; r++) acc[mt][nt][r] = 0.f;

    for (int k0 = 0; k0 < K; k0 += 64) {
        __syncthreads();
#pragma unroll
        for (int i = 0; i < 16; i++) {
            int f4 = t + i * 128;
            int row = f4 >> 4, c4 = f4 & 15;
            float4 v = make_float4(0.f, 0.f, 0.f, 0.f);
            if (m0 + row < J.M) v = *(const float4*)&J.X[(size_t)(m0 + row) * K + k0 + c4 * 4];
            v.x = tf32r(v.x); v.y = tf32r(v.y); v.z = tf32r(v.z); v.w = tf32r(v.w);
            *(float4*)&Xs[row * XP + c4 * 4] = v;
        }
#pragma unroll 8
        for (int i = 0; i < 32; i++) {
            int idx = t + i * 128;
            int k = idx >> 6, n = idx & 63;
            Wt[n * WTP + k] = tf32r(J.W[(size_t)(k0 + k) * 64 + n]);
        }
        __syncthreads();
        tf32_mma(Xs, Wt, rb, gid, tidg, acc);
    }

    float bb[16];
#pragma unroll
    for (int nt = 0; nt < 8; nt++) {
        bb[2*nt]     = J.b[nt * 8 + tidg * 2];
        bb[2*nt + 1] = J.b[nt * 8 + tidg * 2 + 1];
    }
#pragma unroll
    for (int mt = 0; mt < 2; mt++) {
#pragma unroll
        for (int rr = 0; rr < 2; rr++) {
            int row = m0 + rb + mt * 16 + rr * 8 + gid;
            if (row < J.M) {
#pragma unroll
                for (int nt = 0; nt < 8; nt++) {
                    float v0 = acc[mt][nt][2*rr]     + bb[2*nt];
                    float v1 = acc[mt][nt][2*rr + 1] + bb[2*nt + 1];
                    *(float2*)&J.Y[(size_t)row * 64 + nt * 8 + tidg * 2] = make_float2(v0, v1);
                }
            }
        }
    }
}

// ---------------- merged single-pass edge kernel (fp16 gathers, fp32 math) ----------------
__global__ void edge_all(const int* __restrict__ ei0, const int* __restrict__ ei1,
                         const int* __restrict__ ei2, const int* __restrict__ ei3)
{
    int gid = blockIdx.x * blockDim.x + threadIdx.x;
    if (gid >= ET * HD) return;
    int e = gid >> 2, h = gid & 3;

    const int* ei; int er, E, kvoff, qoff, dnoff;
    if (e < E0)                 { ei = ei0; er = e;            E = E0; kvoff = 0;           qoff = N_P;     dnoff = 0; }
    else if (e < E0+E1)         { ei = ei1; er = e - E0;       E = E1; kvoff = N_P;         qoff = 0;       dnoff = N_D; }
    else if (e < E0+E1+E2)      { ei = ei2; er = e - (E0+E1);  E = E2; kvoff = N_P+N_D;     qoff = N_P+N_D; dnoff = N_D+N_P; }
    else                        { ei = ei3; er = e-(E0+E1+E2); E = E3; kvoff = N_P+2*N_D;   qoff = N_P+N_D; dnoff = N_D+N_P+N_S; }

    int src = __ldg(&ei[er]);
    int dst = __ldg(&ei[E + er]);

    const uint4* qp = (const uint4*)&g_qh[(size_t)(qoff + dst) * 64 + h * 16];
    const uint4* kp = (const uint4*)&g_kh[(size_t)(kvoff + src) * 64 + h * 16];
    const uint4* vp = (const uint4*)&g_vh[(size_t)(kvoff + src) * 64 + h * 16];

    __half2 qv[8], kv[8], vv[8];
    *(uint4*)&qv[0] = qp[0]; *(uint4*)&qv[4] = qp[1];
    *(uint4*)&kv[0] = kp[0]; *(uint4*)&kv[4] = kp[1];
    *(uint4*)&vv[0] = vp[0]; *(uint4*)&vv[4] = vp[1];

    float a = 0.f;
#pragma unroll
    for (int jj = 0; jj < 8; jj++) {
        float2 qf = __half22float2(qv[jj]);
        float2 kf = __half22float2(kv[jj]);
        a += qf.x * kf.x + qf.y * kf.y;
    }
    float w = __expf(fminf(a, 60.f));
    atomicAdd(&g_den[(size_t)(dnoff + dst) * 4 + h], w);

    float4* np = (float4*)&g_num[(size_t)(dnoff + dst) * 64 + h * 16];
#pragma unroll
    for (int jj = 0; jj < 4; jj++) {
        float2 v0 = __half22float2(vv[2*jj]);
        float2 v1 = __half22float2(vv[2*jj + 1]);
        atomicAdd(&np[jj], make_float4(v0.x * w, v0.y * w, v1.x * w, v1.y * w));
    }
}

// ---------------- host orchestration ----------------
static inline int cdiv(int a, int b) { return (a + b - 1) / b; }

extern "C" void kernel_launch(void* const* d_in, const int* in_sizes, int n_in,
                              void* d_out, int out_size)
{
    const float* x_p   = (const float*)d_in[0];
    const float* x_d   = (const float*)d_in[1];
    const float* x_s   = (const float*)d_in[2];
    const float* Win_p = (const float*)d_in[3];
    const float* bin_p = (const float*)d_in[4];
    const float* Win_d = (const float*)d_in[5];
    const float* bin_d = (const float*)d_in[6];
    const float* Win_s = (const float*)d_in[7];
    const float* bin_s = (const float*)d_in[8];
    const float* Wk    = (const float*)d_in[9];
    const float* bk    = (const float*)d_in[10];
    const float* Wq    = (const float*)d_in[11];
    const float* bq    = (const float*)d_in[12];
    const float* Wv    = (const float*)d_in[13];
    const float* bv    = (const float*)d_in[14];
    const float* Wa    = (const float*)d_in[15];
    const float* ba    = (const float*)d_in[16];
    const float* a_rel = (const float*)d_in[17];
    const float* m_rel = (const float*)d_in[18];
    const float* p_rel = (const float*)d_in[19];
    const float* skip  = (const float*)d_in[20];
    const int*   ei_pd = (const int*)d_in[21];
    const int*   ei_dp = (const int*)d_in[22];
    const int*   ei_ds = (const int*)d_in[23];
    const int*   ei_ps = (const int*)d_in[24];
    float* out = (float*)d_out;

    float *px, *pnum, *pden, *pWc, *pbc;
    __half *pq, *pkr, *pvr;
    cudaGetSymbolAddress((void**)&px,   g_x);
    cudaGetSymbolAddress((void**)&pq,   g_qh);
    cudaGetSymbolAddress((void**)&pkr,  g_kh);
    cudaGetSymbolAddress((void**)&pvr,  g_vh);
    cudaGetSymbolAddress((void**)&pnum, g_num);
    cudaGetSymbolAddress((void**)&pden, g_den);
    cudaGetSymbolAddress((void**)&pWc,  g_Wc);
    cudaGetSymbolAddress((void**)&pbc,  g_bc);

    const int BP = cdiv(N_P, 128);          // 782
    const int BD = cdiv(N_D, 128);          // 8
    const int BS = cdiv(N_S, 128);          // 40
    const int NG = BP + BD + BS;            // 830
    const size_t kr0 = 0, kr1 = N_P, kr2 = N_P + N_D, kr3 = N_P + 2*N_D;

    combine_weights<<<16, 256>>>(Wk, bk, Wv, bv, a_rel, m_rel, p_rel);

    // input projections (TF32)
    {
        ParamsI P;
        P.job[0] = { x_p, Win_p, bin_p, px,                        N_P, 0,     64 };
        P.job[1] = { x_d, Win_d, bin_d, px + (size_t)N_P*64,       N_D, BP,    128 };
        P.job[2] = { x_s, Win_s, bin_s, px + (size_t)(N_P+N_D)*64, N_S, BP+BD, 64 };
        gemm_input<<<NG, 128>>>(P);
    }

    for (int l = 0; l < 2; l++) {
        // Phase A: TF32 projections (fp16 out) + fused zeroing
        {
            ParamsA P;
            P.nblk_gemm = NG;
            JobA& j0 = P.job[0];
            j0.X = px; j0.M = N_P; j0.blk0 = 0; j0.nT = 5;
            j0.tl[0] = { Wq  + (size_t)(l*3+0)*4096, bq  + (size_t)(l*3+0)*64, pq };
            j0.tl[1] = { pWc + (size_t)(l*8+0)*4096, pbc + (size_t)(l*8+0)*64, pkr + kr0*64 };
            j0.tl[2] = { pWc + (size_t)(l*8+4)*4096, pbc + (size_t)(l*8+4)*64, pvr + kr0*64 };
            j0.tl[3] = { pWc + (size_t)(l*8+3)*4096, pbc + (size_t)(l*8+3)*64, pkr + kr3*64 };
            j0.tl[4] = { pWc + (size_t)(l*8+7)*4096, pbc + (size_t)(l*8+7)*64, pvr + kr3*64 };
            JobA& j1 = P.job[1];
            j1.X = px + (size_t)N_P*64; j1.M = N_D; j1.blk0 = BP; j1.nT = 5;
            j1.tl[0] = { Wq  + (size_t)(l*3+1)*4096, bq  + (size_t)(l*3+1)*64, pq + (size_t)N_P*64 };
            j1.tl[1] = { pWc + (size_t)(l*8+1)*4096, pbc + (size_t)(l*8+1)*64, pkr + kr1*64 };
            j1.tl[2] = { pWc + (size_t)(l*8+5)*4096, pbc + (size_t)(l*8+5)*64, pvr + kr1*64 };
            j1.tl[3] = { pWc + (size_t)(l*8+2)*4096, pbc + (size_t)(l*8+2)*64, pkr + kr2*64 };
            j1.tl[4] = { pWc + (size_t)(l*8+6)*4096, pbc + (size_t)(l*8+6)*64, pvr + kr2*64 };
            JobA& j2 = P.job[2];
            j2.X = px + (size_t)(N_P+N_D)*64; j2.M = N_S; j2.blk0 = BP+BD; j2.nT = 1;
            j2.tl[0] = { Wq + (size_t)(l*3+2)*4096, bq + (size_t)(l*3+2)*64, pq + (size_t)(N_P+N_D)*64 };
            j2.tl[1] = j2.tl[0]; j2.tl[2] = j2.tl[0]; j2.tl[3] = j2.tl[0]; j2.tl[4] = j2.tl[0];
            gemm_phaseA<<<NG + ZB, 128>>>(P);
        }

        // all relations, single launch
        edge_all<<<cdiv(ET * HD, 256), 256>>>(ei_pd, ei_dp, ei_ds, ei_ps);

        // epilogue (fp32 FFMA2, hoisted reciprocals)
        {
            float* Yb = (l == 0) ? px : out;
            ParamsE P;
            P.job[0] = { pnum + (size_t)N_D*64, pden + (size_t)N_D*4, nullptr, nullptr,
                         px, skip + l*3 + 0,
                         Wa + (size_t)(l*3+0)*4096, ba + (size_t)(l*3+0)*64, Yb,
                         N_P, 0 };
            P.job[1] = { pnum, pden, nullptr, nullptr,
                         px + (size_t)N_P*64, skip + l*3 + 1,
                         Wa + (size_t)(l*3+1)*4096, ba + (size_t)(l*3+1)*64, Yb + (size_t)N_P*64,
                         N_D, BP };
            P.job[2] = { pnum + (size_t)(N_D+N_P)*64, pden + (size_t)(N_D+N_P)*4,
                         pnum + (size_t)(N_D+N_P+N_S)*64, pden + (size_t)(N_D+N_P+N_S)*4,
                         px + (size_t)(N_P+N_D)*64, skip + l*3 + 2,
                         Wa + (size_t)(l*3+2)*4096, ba + (size_t)(l*3+2)*64, Yb + (size_t)(N_P+N_D)*64,
                         N_S, BP+BD };
            gemm_epilogue<<<NG, 128>>>(P);
        }
    }
    (void)in_sizes; (void)n_in; (void)out_size;
}

// round 15
// speedup vs baseline: 1.4234x; 1.0249x over previous
#include <cuda_runtime.h>
#include <cuda_fp16.h>
#include <math.h>

// ---------------- problem constants ----------------
#define N_P 100000
#define N_D 1000
#define N_S 5000
#define NT  (N_P + N_D + N_S)
#define CD  64
#define HD  4
#define E0 300000
#define E1 300000
#define E2 100000
#define E3 100000
#define ET (E0 + E1 + E2 + E3)
#define KREL_TOT (2*N_P + 2*N_D)
#define DSTN_TOT (N_D + N_P + 2*N_S)
#define XP 68   // Xs row pitch (floats)
#define WTP 68  // transposed-W row pitch (>=64 extent; 68%32=4 -> conflict-free reads)
#define ZB 222
#define DEN4 (DSTN_TOT)
#define NUM4 (DSTN_TOT * 16)
#define TOT4 (DEN4 + NUM4)

typedef unsigned long long u64;

// ---------------- device scratch ----------------
__device__ __align__(16) float  g_x[NT * CD];
__device__ __align__(16) __half g_qh[NT * CD];
__device__ __align__(16) __half g_kh[KREL_TOT * CD];
__device__ __align__(16) __half g_vh[KREL_TOT * CD];
__device__ __align__(16) float  g_den[DSTN_TOT * HD];
__device__ __align__(16) float  g_num[DSTN_TOT * CD];
__device__ __align__(16) float  g_Wc[16 * CD * CD];
__device__ __align__(16) float  g_bc[16 * CD];

// ---------------- helpers ----------------
__device__ __forceinline__ u64 pack2(float x) {
    u64 r; asm("mov.b64 %0, {%1, %1};" : "=l"(r) : "f"(x)); return r;
}
__device__ __forceinline__ u64 fma2(u64 a, u64 b, u64 c) {
    u64 d; asm("fma.rn.f32x2 %0, %1, %2, %3;" : "=l"(d) : "l"(a), "l"(b), "l"(c)); return d;
}
__device__ __forceinline__ float2 unpack2(u64 a) {
    float2 f; asm("mov.b64 {%0, %1}, %2;" : "=f"(f.x), "=f"(f.y) : "l"(a)); return f;
}
__device__ __forceinline__ float tf32r(float x) {   // round-to-nearest tf32
    unsigned r; asm("cvt.rna.tf32.f32 %0, %1;" : "=r"(r) : "f"(x));
    return __uint_as_float(r);
}
__device__ __forceinline__ float gelu_exact(float x) {
    return 0.5f * x * (1.0f + erff(x * 0.70710678118654752f));
}

// ---------------- TF32 warp-MMA core: 128x64 @ 64x64 (accumulating) ----------------
__device__ __forceinline__ void tf32_mma(const float* Xs, const float* Wt,
                                         int rb, int gid, int tidg,
                                         float acc[2][8][4])
{
#pragma unroll
    for (int k0 = 0; k0 < 64; k0 += 8) {
        unsigned a[2][4];
#pragma unroll
        for (int mt = 0; mt < 2; mt++) {
            const float* xp = &Xs[(rb + mt * 16 + gid) * XP + k0 + tidg];
            a[mt][0] = __float_as_uint(xp[0]);
            a[mt][1] = __float_as_uint(xp[8 * XP]);
            a[mt][2] = __float_as_uint(xp[4]);
            a[mt][3] = __float_as_uint(xp[8 * XP + 4]);
        }
        unsigned b[8][2];
#pragma unroll
        for (int nt = 0; nt < 8; nt++) {
            const float* wp = &Wt[(nt * 8 + gid) * WTP + k0 + tidg];
            b[nt][0] = __float_as_uint(wp[0]);
            b[nt][1] = __float_as_uint(wp[4]);
        }
#pragma unroll
        for (int mt = 0; mt < 2; mt++)
#pragma unroll
            for (int nt = 0; nt < 8; nt++)
                asm volatile(
                    "mma.sync.aligned.m16n8k8.row.col.f32.tf32.tf32.f32 "
                    "{%0,%1,%2,%3}, {%4,%5,%6,%7}, {%8,%9}, {%0,%1,%2,%3};"
                    : "+f"(acc[mt][nt][0]), "+f"(acc[mt][nt][1]),
                      "+f"(acc[mt][nt][2]), "+f"(acc[mt][nt][3])
                    : "r"(a[mt][0]), "r"(a[mt][1]), "r"(a[mt][2]), "r"(a[mt][3]),
                      "r"(b[nt][0]), "r"(b[nt][1]));
    }
}

// ---------------- fp32 FFMA2 GEMM core (epilogue) ----------------
__device__ __forceinline__ void mma_core(const float* Xs, const float* Ws,
                                         int ty, int tx, u64 acc[8][4])
{
#pragma unroll 2
    for (int kk = 0; kk < 64; kk += 4) {
        float4 xv[8];
#pragma unroll
        for (int i = 0; i < 8; i++)
            xv[i] = *(const float4*)&Xs[(ty + i * 16) * XP + kk];
#pragma unroll
        for (int c = 0; c < 4; c++) {
            ulonglong2 wA = *(const ulonglong2*)&Ws[(kk + c) * 64 + tx * 8];
            ulonglong2 wB = *(const ulonglong2*)&Ws[(kk + c) * 64 + tx * 8 + 4];
            u64 w0 = wA.x, w1 = wA.y, w2 = wB.x, w3 = wB.y;
#pragma unroll
            for (int i = 0; i < 8; i++) {
                float xs = (c == 0) ? xv[i].x : (c == 1) ? xv[i].y
                         : (c == 2) ? xv[i].z : xv[i].w;
                u64 x2 = pack2(xs);
                acc[i][0] = fma2(x2, w0, acc[i][0]);
                acc[i][1] = fma2(x2, w1, acc[i][1]);
                acc[i][2] = fma2(x2, w2, acc[i][2]);
                acc[i][3] = fma2(x2, w3, acc[i][3]);
            }
        }
    }
}

// ---------------- combine weights ----------------
__global__ void combine_weights(const float* __restrict__ Wk, const float* __restrict__ bk,
                                const float* __restrict__ Wv, const float* __restrict__ bv,
                                const float* __restrict__ a_rel, const float* __restrict__ m_rel,
                                const float* __restrict__ p_rel)
{
    int blk = blockIdx.x;
    int l  = blk >> 3;
    int kv = (blk >> 2) & 1;
    int r  = blk & 3;
    const int st_tab[4] = {0, 1, 1, 0};
    int st = st_tab[r];

    const float* Wbase = (kv == 0 ? Wk : Wv) + (size_t)(l*3 + st) * CD * CD;
    const float* bbase = (kv == 0 ? bk : bv) + (size_t)(l*3 + st) * CD;
    const float* rel   = (kv == 0 ? a_rel : m_rel) + (size_t)(l*4 + r) * HD * 256;

    __shared__ float srel[HD * 256];
    __shared__ float sscale[HD];
    int t = threadIdx.x; // 256
    for (int i = t; i < HD*256; i += 256) srel[i] = rel[i];
    if (t < HD) sscale[t] = (kv == 0) ? p_rel[(l*4 + r) * HD + t] * 0.25f : 1.0f;
    __syncthreads();

    float* Wc = g_Wc + (size_t)blk * CD * CD;
    float* bc = g_bc + (size_t)blk * CD;

    int c = t >> 2, h = t & 3;
    float wrow[16];
#pragma unroll
    for (int d = 0; d < 16; d++) wrow[d] = Wbase[c*CD + h*16 + d];
    float sc = sscale[h];
#pragma unroll
    for (int e = 0; e < 16; e++) {
        float s = 0.f;
#pragma unroll
        for (int d = 0; d < 16; d++) s += wrow[d] * srel[h*256 + d*16 + e];
        Wc[c*CD + h*16 + e] = s * sc;
    }
    if (t < CD) {
        int hh = t >> 4, ee = t & 15;
        float s = 0.f;
#pragma unroll
        for (int d = 0; d < 16; d++) s += bbase[hh*16 + d] * srel[hh*256 + d*16 + ee];
        bc[t] = s * sscale[hh];
    }
}

// ---------------- job descriptors ----------------
struct TileW { const float* W; const float* b; __half* Y; };
struct JobA  { const float* X; int M; int blk0; int nT; TileW tl[5]; };
struct ParamsA { JobA job[3]; int nblk_gemm; };

struct JobE {
    const float* num0; const float* den0;
    const float* num1; const float* den1;
    const float* xold; const float* skipp;
    const float* W; const float* b; float* Y;
    int M; int blk0;
};
struct ParamsE { JobE job[3]; };

struct JobI { const float* X; const float* W; const float* b; float* Y; int M; int blk0; int K; };
struct ParamsI { JobI job[3]; };

// ---------------- Phase A: TF32 -> fp16 outputs (smem-staged stores) + fused zeroing ----------------
__global__ void __launch_bounds__(128)
gemm_phaseA(ParamsA P)
{
    __shared__ float Xs[128 * XP];
    __shared__ float Wt[64 * WTP];   // reused as fp16 output stage after MMA
    int bx = blockIdx.x;
    int t = threadIdx.x;

    if (bx >= P.nblk_gemm) {
        int zb = bx - P.nblk_gemm;
        float4 z = make_float4(0.f, 0.f, 0.f, 0.f);
        float4* dp = (float4*)g_den;
        float4* np = (float4*)g_num;
        for (int i = zb * 128 + t; i < TOT4; i += ZB * 128) {
            if (i < DEN4) dp[i] = z;
            else          np[i - DEN4] = z;
        }
        return;
    }

    int j = (bx >= P.job[2].blk0) ? 2 : (bx >= P.job[1].blk0) ? 1 : 0;
    const JobA& J = P.job[j];
    int m0 = (bx - J.blk0) * 128;
    const int lane = t & 31, warp = t >> 5;
    const int gid = lane >> 2, tidg = lane & 3;
    const int rb = warp * 32;

#pragma unroll
    for (int i = 0; i < 16; i++) {
        int f4 = t + i * 128;
        int row = f4 >> 4, c4 = f4 & 15;
        float4 v = make_float4(0.f, 0.f, 0.f, 0.f);
        if (m0 + row < J.M) v = *(const float4*)&J.X[(size_t)(m0 + row) * 64 + c4 * 4];
        v.x = tf32r(v.x); v.y = tf32r(v.y); v.z = tf32r(v.z); v.w = tf32r(v.w);
        *(float4*)&Xs[row * XP + c4 * 4] = v;
    }

    for (int ti = 0; ti < J.nT; ti++) {
        __syncthreads();               // Xs ready / prev stage reads done
        const float* __restrict__ W = J.tl[ti].W;
#pragma unroll 8
        for (int i = 0; i < 32; i++) {
            int idx = t + i * 128;
            int k = idx >> 6, n = idx & 63;
            Wt[n * WTP + k] = tf32r(W[idx]);
        }
        __syncthreads();

        float acc[2][8][4];
#pragma unroll
        for (int mt = 0; mt < 2; mt++)
#pragma unroll
            for (int nt = 0; nt < 8; nt++)
#pragma unroll
                for (int r = 0; r < 4; r++) acc[mt][nt][r] = 0.f;

        tf32_mma(Xs, Wt, rb, gid, tidg, acc);

        const float* bias = J.tl[ti].b;
        float bb[16];
#pragma unroll
        for (int nt = 0; nt < 8; nt++) {
            bb[2*nt]     = bias[nt * 8 + tidg * 2];
            bb[2*nt + 1] = bias[nt * 8 + tidg * 2 + 1];
        }

        __syncthreads();               // all warps finished reading Wt
        __half* stg = (__half*)Wt;     // 128 rows x 64 halves, XOR-swizzled
#pragma unroll
        for (int mt = 0; mt < 2; mt++) {
#pragma unroll
            for (int rr = 0; rr < 2; rr++) {
                int rl = rb + mt * 16 + rr * 8 + gid;   // 0..127
#pragma unroll
                for (int nt = 0; nt < 8; nt++) {
                    float v0 = acc[mt][nt][2*rr]     + bb[2*nt];
                    float v1 = acc[mt][nt][2*rr + 1] + bb[2*nt + 1];
                    int col = (nt * 8 + tidg * 2) ^ ((rl & 7) * 8);
                    *(__half2*)&stg[rl * 64 + col] = __floats2half2_rn(v0, v1);
                }
            }
        }
        __syncthreads();

        __half* Y = J.tl[ti].Y;
#pragma unroll
        for (int i = 0; i < 8; i++) {
            int idx = t + i * 128;      // 1024 uint4 slots
            int row = idx >> 3, c8 = idx & 7;
            uint4 val = *(const uint4*)&stg[row * 64 + ((c8 * 8) ^ ((row & 7) * 8))];
            if (m0 + row < J.M)
                *(uint4*)&Y[(size_t)(m0 + row) * 64 + c8 * 8] = val;
        }
    }
}

// ---------------- Epilogue (128 thr, fp32 FFMA2; hoisted reciprocals + float4 fill) ----------------
__global__ void __launch_bounds__(128)
gemm_epilogue(ParamsE P)
{
    __shared__ float Xs[128 * XP];
    __shared__ __align__(16) float Ws[64 * 64];
    __shared__ float sinv[128 * 8];
    int bx = blockIdx.x;
    int j = (bx >= P.job[2].blk0) ? 2 : (bx >= P.job[1].blk0) ? 1 : 0;
    const JobE& J = P.job[j];
    int m0 = (bx - J.blk0) * 128;
    int t = threadIdx.x;
    const int ty = t >> 3, tx = t & 7;

#pragma unroll
    for (int i = 0; i < 4; i++) {
        int idx = t + i * 128;
        int row = idx >> 2, h = idx & 3;
        int n = m0 + row;
        float v0 = 0.f, v1 = 0.f;
        if (n < J.M) {
            v0 = 1.0f / (J.den0[(size_t)n * 4 + h] + 1e-16f);
            if (J.den1) v1 = 1.0f / (J.den1[(size_t)n * 4 + h] + 1e-16f);
        }
        sinv[row * 8 + h]     = v0;
        sinv[row * 8 + 4 + h] = v1;
    }
    __syncthreads();

#pragma unroll
    for (int i = 0; i < 16; i++) {
        int idx = t + i * 128;
        int row = idx >> 4, c4 = idx & 15;
        int n = m0 + row;
        float4 v = make_float4(0.f, 0.f, 0.f, 0.f);
        if (n < J.M) {
            int h = c4 >> 2;
            float inv0 = sinv[row * 8 + h];
            float4 a = *(const float4*)&J.num0[(size_t)n * 64 + c4 * 4];
            v.x = a.x * inv0; v.y = a.y * inv0; v.z = a.z * inv0; v.w = a.w * inv0;
            if (J.num1) {
                float inv1 = sinv[row * 8 + 4 + h];
                float4 b = *(const float4*)&J.num1[(size_t)n * 64 + c4 * 4];
                v.x += b.x * inv1; v.y += b.y * inv1;
                v.z += b.z * inv1; v.w += b.w * inv1;
            }
            v.x = gelu_exact(v.x); v.y = gelu_exact(v.y);
            v.z = gelu_exact(v.z); v.w = gelu_exact(v.w);
        }
        *(float4*)&Xs[row * XP + c4 * 4] = v;
    }
#pragma unroll
    for (int i = 0; i < 8; i++) {
        int f4 = (t + i * 128) * 4;
        *(float4*)&Ws[f4] = *(const float4*)&J.W[f4];
    }
    __syncthreads();

    u64 acc[8][4];
#pragma unroll
    for (int i = 0; i < 8; i++)
#pragma unroll
        for (int k = 0; k < 4; k++) acc[i][k] = 0ull;

    mma_core(Xs, Ws, ty, tx, acc);

    float bb[8];
#pragma unroll
    for (int q = 0; q < 8; q++) bb[q] = J.b[tx * 8 + q];
    float s = 1.0f / (1.0f + expf(-J.skipp[0]));
    float om = 1.0f - s;

#pragma unroll
    for (int i = 0; i < 8; i++) {
        int row = m0 + ty + i * 16;
        if (row < J.M) {
            float o[8];
#pragma unroll
            for (int k = 0; k < 4; k++) {
                float2 p = unpack2(acc[i][k]);
                o[2*k] = p.x + bb[2*k]; o[2*k+1] = p.y + bb[2*k+1];
            }
            float4 x0 = *(const float4*)&J.xold[(size_t)row * 64 + tx * 8];
            float4 x1 = *(const float4*)&J.xold[(size_t)row * 64 + tx * 8 + 4];
            o[0] = s*o[0] + om*x0.x; o[1] = s*o[1] + om*x0.y;
            o[2] = s*o[2] + om*x0.z; o[3] = s*o[3] + om*x0.w;
            o[4] = s*o[4] + om*x1.x; o[5] = s*o[5] + om*x1.y;
            o[6] = s*o[6] + om*x1.z; o[7] = s*o[7] + om*x1.w;
            *(float4*)&J.Y[(size_t)row * 64 + tx * 8]     = make_float4(o[0], o[1], o[2], o[3]);
            *(float4*)&J.Y[(size_t)row * 64 + tx * 8 + 4] = make_float4(o[4], o[5], o[6], o[7]);
        }
    }
}

// ---------------- Input projections: TF32 (runtime K, fp32 out) ----------------
__global__ void __launch_bounds__(128)
gemm_input(ParamsI P)
{
    __shared__ float Xs[128 * XP];
    __shared__ float Wt[64 * WTP];
    int bx = blockIdx.x;
    int j = (bx >= P.job[2].blk0) ? 2 : (bx >= P.job[1].blk0) ? 1 : 0;
    const JobI& J = P.job[j];
    int m0 = (bx - J.blk0) * 128;
    int t = threadIdx.x;
    const int lane = t & 31, warp = t >> 5;
    const int gid = lane >> 2, tidg = lane & 3;
    const int rb = warp * 32;
    const int K = J.K;

    float acc[2][8][4];
#pragma unroll
    for (int mt = 0; mt < 2; mt++)
#pragma unroll
        for (int nt = 0; nt < 8; nt++)
#pragma unroll
            for (int r = 0; r < 4; r++) acc[mt][nt][r] = 0.f;

    for (int k0 = 0; k0 < K; k0 += 64) {
        __syncthreads();
#pragma unroll
        for (int i = 0; i < 16; i++) {
            int f4 = t + i * 128;
            int row = f4 >> 4, c4 = f4 & 15;
            float4 v = make_float4(0.f, 0.f, 0.f, 0.f);
            if (m0 + row < J.M) v = *(const float4*)&J.X[(size_t)(m0 + row) * K + k0 + c4 * 4];
            v.x = tf32r(v.x); v.y = tf32r(v.y); v.z = tf32r(v.z); v.w = tf32r(v.w);
            *(float4*)&Xs[row * XP + c4 * 4] = v;
        }
#pragma unroll 8
        for (int i = 0; i < 32; i++) {
            int idx = t + i * 128;
            int k = idx >> 6, n = idx & 63;
            Wt[n * WTP + k] = tf32r(J.W[(size_t)(k0 + k) * 64 + n]);
        }
        __syncthreads();
        tf32_mma(Xs, Wt, rb, gid, tidg, acc);
    }

    float bb[16];
#pragma unroll
    for (int nt = 0; nt < 8; nt++) {
        bb[2*nt]     = J.b[nt * 8 + tidg * 2];
        bb[2*nt + 1] = J.b[nt * 8 + tidg * 2 + 1];
    }
#pragma unroll
    for (int mt = 0; mt < 2; mt++) {
#pragma unroll
        for (int rr = 0; rr < 2; rr++) {
            int row = m0 + rb + mt * 16 + rr * 8 + gid;
            if (row < J.M) {
#pragma unroll
                for (int nt = 0; nt < 8; nt++) {
                    float v0 = acc[mt][nt][2*rr]     + bb[2*nt];
                    float v1 = acc[mt][nt][2*rr + 1] + bb[2*nt + 1];
                    *(float2*)&J.Y[(size_t)row * 64 + nt * 8 + tidg * 2] = make_float2(v0, v1);
                }
            }
        }
    }
}

// ---------------- merged single-pass edge kernel (fp16 gathers, fp32 math) ----------------
__global__ void edge_all(const int* __restrict__ ei0, const int* __restrict__ ei1,
                         const int* __restrict__ ei2, const int* __restrict__ ei3)
{
    int gid = blockIdx.x * blockDim.x + threadIdx.x;
    if (gid >= ET * HD) return;
    int e = gid >> 2, h = gid & 3;

    const int* ei; int er, E, kvoff, qoff, dnoff;
    if (e < E0)                 { ei = ei0; er = e;            E = E0; kvoff = 0;           qoff = N_P;     dnoff = 0; }
    else if (e < E0+E1)         { ei = ei1; er = e - E0;       E = E1; kvoff = N_P;         qoff = 0;       dnoff = N_D; }
    else if (e < E0+E1+E2)      { ei = ei2; er = e - (E0+E1);  E = E2; kvoff = N_P+N_D;     qoff = N_P+N_D; dnoff = N_D+N_P; }
    else                        { ei = ei3; er = e-(E0+E1+E2); E = E3; kvoff = N_P+2*N_D;   qoff = N_P+N_D; dnoff = N_D+N_P+N_S; }

    int src = __ldg(&ei[er]);
    int dst = __ldg(&ei[E + er]);

    const uint4* qp = (const uint4*)&g_qh[(size_t)(qoff + dst) * 64 + h * 16];
    const uint4* kp = (const uint4*)&g_kh[(size_t)(kvoff + src) * 64 + h * 16];
    const uint4* vp = (const uint4*)&g_vh[(size_t)(kvoff + src) * 64 + h * 16];

    __half2 qv[8], kv[8], vv[8];
    *(uint4*)&qv[0] = qp[0]; *(uint4*)&qv[4] = qp[1];
    *(uint4*)&kv[0] = kp[0]; *(uint4*)&kv[4] = kp[1];
    *(uint4*)&vv[0] = vp[0]; *(uint4*)&vv[4] = vp[1];

    float a = 0.f;
#pragma unroll
    for (int jj = 0; jj < 8; jj++) {
        float2 qf = __half22float2(qv[jj]);
        float2 kf = __half22float2(kv[jj]);
        a += qf.x * kf.x + qf.y * kf.y;
    }
    float w = __expf(fminf(a, 60.f));

    // combine the 4 per-head den adds into one RED.128 (lanes h=0..3 share an edge)
    float w1 = __shfl_sync(0xFFFFFFFFu, w, 1, 4);
    float w2 = __shfl_sync(0xFFFFFFFFu, w, 2, 4);
    float w3 = __shfl_sync(0xFFFFFFFFu, w, 3, 4);
    if (h == 0)
        atomicAdd((float4*)&g_den[(size_t)(dnoff + dst) * 4], make_float4(w, w1, w2, w3));

    float4* np = (float4*)&g_num[(size_t)(dnoff + dst) * 64 + h * 16];
#pragma unroll
    for (int jj = 0; jj < 4; jj++) {
        float2 v0 = __half22float2(vv[2*jj]);
        float2 v1 = __half22float2(vv[2*jj + 1]);
        atomicAdd(&np[jj], make_float4(v0.x * w, v0.y * w, v1.x * w, v1.y * w));
    }
}

// ---------------- host orchestration ----------------
static inline int cdiv(int a, int b) { return (a + b - 1) / b; }

extern "C" void kernel_launch(void* const* d_in, const int* in_sizes, int n_in,
                              void* d_out, int out_size)
{
    const float* x_p   = (const float*)d_in[0];
    const float* x_d   = (const float*)d_in[1];
    const float* x_s   = (const float*)d_in[2];
    const float* Win_p = (const float*)d_in[3];
    const float* bin_p = (const float*)d_in[4];
    const float* Win_d = (const float*)d_in[5];
    const float* bin_d = (const float*)d_in[6];
    const float* Win_s = (const float*)d_in[7];
    const float* bin_s = (const float*)d_in[8];
    const float* Wk    = (const float*)d_in[9];
    const float* bk    = (const float*)d_in[10];
    const float* Wq    = (const float*)d_in[11];
    const float* bq    = (const float*)d_in[12];
    const float* Wv    = (const float*)d_in[13];
    const float* bv    = (const float*)d_in[14];
    const float* Wa    = (const float*)d_in[15];
    const float* ba    = (const float*)d_in[16];
    const float* a_rel = (const float*)d_in[17];
    const float* m_rel = (const float*)d_in[18];
    const float* p_rel = (const float*)d_in[19];
    const float* skip  = (const float*)d_in[20];
    const int*   ei_pd = (const int*)d_in[21];
    const int*   ei_dp = (const int*)d_in[22];
    const int*   ei_ds = (const int*)d_in[23];
    const int*   ei_ps = (const int*)d_in[24];
    float* out = (float*)d_out;

    float *px, *pnum, *pden, *pWc, *pbc;
    __half *pq, *pkr, *pvr;
    cudaGetSymbolAddress((void**)&px,   g_x);
    cudaGetSymbolAddress((void**)&pq,   g_qh);
    cudaGetSymbolAddress((void**)&pkr,  g_kh);
    cudaGetSymbolAddress((void**)&pvr,  g_vh);
    cudaGetSymbolAddress((void**)&pnum, g_num);
    cudaGetSymbolAddress((void**)&pden, g_den);
    cudaGetSymbolAddress((void**)&pWc,  g_Wc);
    cudaGetSymbolAddress((void**)&pbc,  g_bc);

    const int BP = cdiv(N_P, 128);          // 782
    const int BD = cdiv(N_D, 128);          // 8
    const int BS = cdiv(N_S, 128);          // 40
    const int NG = BP + BD + BS;            // 830
    const size_t kr0 = 0, kr1 = N_P, kr2 = N_P + N_D, kr3 = N_P + 2*N_D;

    combine_weights<<<16, 256>>>(Wk, bk, Wv, bv, a_rel, m_rel, p_rel);

    // input projections (TF32)
    {
        ParamsI P;
        P.job[0] = { x_p, Win_p, bin_p, px,                        N_P, 0,     64 };
        P.job[1] = { x_d, Win_d, bin_d, px + (size_t)N_P*64,       N_D, BP,    128 };
        P.job[2] = { x_s, Win_s, bin_s, px + (size_t)(N_P+N_D)*64, N_S, BP+BD, 64 };
        gemm_input<<<NG, 128>>>(P);
    }

    for (int l = 0; l < 2; l++) {
        // Phase A: TF32 projections (fp16 out, smem-staged stores) + fused zeroing
        {
            ParamsA P;
            P.nblk_gemm = NG;
            JobA& j0 = P.job[0];
            j0.X = px; j0.M = N_P; j0.blk0 = 0; j0.nT = 5;
            j0.tl[0] = { Wq  + (size_t)(l*3+0)*4096, bq  + (size_t)(l*3+0)*64, pq };
            j0.tl[1] = { pWc + (size_t)(l*8+0)*4096, pbc + (size_t)(l*8+0)*64, pkr + kr0*64 };
            j0.tl[2] = { pWc + (size_t)(l*8+4)*4096, pbc + (size_t)(l*8+4)*64, pvr + kr0*64 };
            j0.tl[3] = { pWc + (size_t)(l*8+3)*4096, pbc + (size_t)(l*8+3)*64, pkr + kr3*64 };
            j0.tl[4] = { pWc + (size_t)(l*8+7)*4096, pbc + (size_t)(l*8+7)*64, pvr + kr3*64 };
            JobA& j1 = P.job[1];
            j1.X = px + (size_t)N_P*64; j1.M = N_D; j1.blk0 = BP; j1.nT = 5;
            j1.tl[0] = { Wq  + (size_t)(l*3+1)*4096, bq  + (size_t)(l*3+1)*64, pq + (size_t)N_P*64 };
            j1.tl[1] = { pWc + (size_t)(l*8+1)*4096, pbc + (size_t)(l*8+1)*64, pkr + kr1*64 };
            j1.tl[2] = { pWc + (size_t)(l*8+5)*4096, pbc + (size_t)(l*8+5)*64, pvr + kr1*64 };
            j1.tl[3] = { pWc + (size_t)(l*8+2)*4096, pbc + (size_t)(l*8+2)*64, pkr + kr2*64 };
            j1.tl[4] = { pWc + (size_t)(l*8+6)*4096, pbc + (size_t)(l*8+6)*64, pvr + kr2*64 };
            JobA& j2 = P.job[2];
            j2.X = px + (size_t)(N_P+N_D)*64; j2.M = N_S; j2.blk0 = BP+BD; j2.nT = 1;
            j2.tl[0] = { Wq + (size_t)(l*3+2)*4096, bq + (size_t)(l*3+2)*64, pq + (size_t)(N_P+N_D)*64 };
            j2.tl[1] = j2.tl[0]; j2.tl[2] = j2.tl[0]; j2.tl[3] = j2.tl[0]; j2.tl[4] = j2.tl[0];
            gemm_phaseA<<<NG + ZB, 128>>>(P);
        }

        // all relations, single launch
        edge_all<<<cdiv(ET * HD, 256), 256>>>(ei_pd, ei_dp, ei_ds, ei_ps);

        // epilogue (fp32 FFMA2, hoisted reciprocals)
        {
            float* Yb = (l == 0) ? px : out;
            ParamsE P;
            P.job[0] = { pnum + (size_t)N_D*64, pden + (size_t)N_D*4, nullptr, nullptr,
                         px, skip + l*3 + 0,
                         Wa + (size_t)(l*3+0)*4096, ba + (size_t)(l*3+0)*64, Yb,
                         N_P, 0 };
            P.job[1] = { pnum, pden, nullptr, nullptr,
                         px + (size_t)N_P*64, skip + l*3 + 1,
                         Wa + (size_t)(l*3+1)*4096, ba + (size_t)(l*3+1)*64, Yb + (size_t)N_P*64,
                         N_D, BP };
            P.job[2] = { pnum + (size_t)(N_D+N_P)*64, pden + (size_t)(N_D+N_P)*4,
                         pnum + (size_t)(N_D+N_P+N_S)*64, pden + (size_t)(N_D+N_P+N_S)*4,
                         px + (size_t)(N_P+N_D)*64, skip + l*3 + 2,
                         Wa + (size_t)(l*3+2)*4096, ba + (size_t)(l*3+2)*64, Yb + (size_t)(N_P+N_D)*64,
                         N_S, BP+BD };
            gemm_epilogue<<<NG, 128>>>(P);
        }
    }
    (void)in_sizes; (void)n_in; (void)out_size;
}

// round 16
// speedup vs baseline: 1.4318x; 1.0059x over previous
#include <cuda_runtime.h>
#include <cuda_fp16.h>
#include <math.h>

// ---------------- problem constants ----------------
#define N_P 100000
#define N_D 1000
#define N_S 5000
#define NT  (N_P + N_D + N_S)
#define CD  64
#define HD  4
#define E0 300000
#define E1 300000
#define E2 100000
#define E3 100000
#define ET (E0 + E1 + E2 + E3)
#define KREL_TOT (2*N_P + 2*N_D)
#define DSTN_TOT (N_D + N_P + 2*N_S)
#define XP 68
#define WTP 68
#define ZB 222
#define NREP 15                         // extra replicas for drug-dst accumulators
#define DEN4 (DSTN_TOT)                 // float4 count of g_den
#define NUM4 (DSTN_TOT * 16)            // float4 count of g_num
#define DR4  (NREP * N_D)               // float4 count of g_denrepl
#define NR4  (NREP * N_D * 16)          // float4 count of g_numrepl
#define TOTR4 (DEN4 + NUM4 + DR4 + NR4)

typedef unsigned long long u64;

// ---------------- device scratch ----------------
__device__ __align__(16) float  g_x[NT * CD];
__device__ __align__(16) __half g_qh[NT * CD];
__device__ __align__(16) __half g_kh[KREL_TOT * CD];
__device__ __align__(16) __half g_vh[KREL_TOT * CD];
__device__ __align__(16) float  g_den[DSTN_TOT * HD];
__device__ __align__(16) float  g_num[DSTN_TOT * CD];
__device__ __align__(16) float  g_denrepl[NREP * N_D * HD];
__device__ __align__(16) float  g_numrepl[NREP * N_D * CD];
__device__ __align__(16) float  g_Wc[16 * CD * CD];
__device__ __align__(16) float  g_bc[16 * CD];

// ---------------- helpers ----------------
__device__ __forceinline__ u64 pack2(float x) {
    u64 r; asm("mov.b64 %0, {%1, %1};" : "=l"(r) : "f"(x)); return r;
}
__device__ __forceinline__ u64 fma2(u64 a, u64 b, u64 c) {
    u64 d; asm("fma.rn.f32x2 %0, %1, %2, %3;" : "=l"(d) : "l"(a), "l"(b), "l"(c)); return d;
}
__device__ __forceinline__ float2 unpack2(u64 a) {
    float2 f; asm("mov.b64 {%0, %1}, %2;" : "=f"(f.x), "=f"(f.y) : "l"(a)); return f;
}
__device__ __forceinline__ float tf32r(float x) {
    unsigned r; asm("cvt.rna.tf32.f32 %0, %1;" : "=r"(r) : "f"(x));
    return __uint_as_float(r);
}
__device__ __forceinline__ float gelu_exact(float x) {
    return 0.5f * x * (1.0f + erff(x * 0.70710678118654752f));
}

// ---------------- TF32 warp-MMA core ----------------
__device__ __forceinline__ void tf32_mma(const float* Xs, const float* Wt,
                                         int rb, int gid, int tidg,
                                         float acc[2][8][4])
{
#pragma unroll
    for (int k0 = 0; k0 < 64; k0 += 8) {
        unsigned a[2][4];
#pragma unroll
        for (int mt = 0; mt < 2; mt++) {
            const float* xp = &Xs[(rb + mt * 16 + gid) * XP + k0 + tidg];
            a[mt][0] = __float_as_uint(xp[0]);
            a[mt][1] = __float_as_uint(xp[8 * XP]);
            a[mt][2] = __float_as_uint(xp[4]);
            a[mt][3] = __float_as_uint(xp[8 * XP + 4]);
        }
        unsigned b[8][2];
#pragma unroll
        for (int nt = 0; nt < 8; nt++) {
            const float* wp = &Wt[(nt * 8 + gid) * WTP + k0 + tidg];
            b[nt][0] = __float_as_uint(wp[0]);
            b[nt][1] = __float_as_uint(wp[4]);
        }
#pragma unroll
        for (int mt = 0; mt < 2; mt++)
#pragma unroll
            for (int nt = 0; nt < 8; nt++)
                asm volatile(
                    "mma.sync.aligned.m16n8k8.row.col.f32.tf32.tf32.f32 "
                    "{%0,%1,%2,%3}, {%4,%5,%6,%7}, {%8,%9}, {%0,%1,%2,%3};"
                    : "+f"(acc[mt][nt][0]), "+f"(acc[mt][nt][1]),
                      "+f"(acc[mt][nt][2]), "+f"(acc[mt][nt][3])
                    : "r"(a[mt][0]), "r"(a[mt][1]), "r"(a[mt][2]), "r"(a[mt][3]),
                      "r"(b[nt][0]), "r"(b[nt][1]));
    }
}

// ---------------- fp32 FFMA2 GEMM core (epilogue) ----------------
__device__ __forceinline__ void mma_core(const float* Xs, const float* Ws,
                                         int ty, int tx, u64 acc[8][4])
{
#pragma unroll 2
    for (int kk = 0; kk < 64; kk += 4) {
        float4 xv[8];
#pragma unroll
        for (int i = 0; i < 8; i++)
            xv[i] = *(const float4*)&Xs[(ty + i * 16) * XP + kk];
#pragma unroll
        for (int c = 0; c < 4; c++) {
            ulonglong2 wA = *(const ulonglong2*)&Ws[(kk + c) * 64 + tx * 8];
            ulonglong2 wB = *(const ulonglong2*)&Ws[(kk + c) * 64 + tx * 8 + 4];
            u64 w0 = wA.x, w1 = wA.y, w2 = wB.x, w3 = wB.y;
#pragma unroll
            for (int i = 0; i < 8; i++) {
                float xs = (c == 0) ? xv[i].x : (c == 1) ? xv[i].y
                         : (c == 2) ? xv[i].z : xv[i].w;
                u64 x2 = pack2(xs);
                acc[i][0] = fma2(x2, w0, acc[i][0]);
                acc[i][1] = fma2(x2, w1, acc[i][1]);
                acc[i][2] = fma2(x2, w2, acc[i][2]);
                acc[i][3] = fma2(x2, w3, acc[i][3]);
            }
        }
    }
}

// ---------------- combine weights ----------------
__global__ void combine_weights(const float* __restrict__ Wk, const float* __restrict__ bk,
                                const float* __restrict__ Wv, const float* __restrict__ bv,
                                const float* __restrict__ a_rel, const float* __restrict__ m_rel,
                                const float* __restrict__ p_rel)
{
    int blk = blockIdx.x;
    int l  = blk >> 3;
    int kv = (blk >> 2) & 1;
    int r  = blk & 3;
    const int st_tab[4] = {0, 1, 1, 0};
    int st = st_tab[r];

    const float* Wbase = (kv == 0 ? Wk : Wv) + (size_t)(l*3 + st) * CD * CD;
    const float* bbase = (kv == 0 ? bk : bv) + (size_t)(l*3 + st) * CD;
    const float* rel   = (kv == 0 ? a_rel : m_rel) + (size_t)(l*4 + r) * HD * 256;

    __shared__ float srel[HD * 256];
    __shared__ float sscale[HD];
    int t = threadIdx.x;
    for (int i = t; i < HD*256; i += 256) srel[i] = rel[i];
    if (t < HD) sscale[t] = (kv == 0) ? p_rel[(l*4 + r) * HD + t] * 0.25f : 1.0f;
    __syncthreads();

    float* Wc = g_Wc + (size_t)blk * CD * CD;
    float* bc = g_bc + (size_t)blk * CD;

    int c = t >> 2, h = t & 3;
    float wrow[16];
#pragma unroll
    for (int d = 0; d < 16; d++) wrow[d] = Wbase[c*CD + h*16 + d];
    float sc = sscale[h];
#pragma unroll
    for (int e = 0; e < 16; e++) {
        float s = 0.f;
#pragma unroll
        for (int d = 0; d < 16; d++) s += wrow[d] * srel[h*256 + d*16 + e];
        Wc[c*CD + h*16 + e] = s * sc;
    }
    if (t < CD) {
        int hh = t >> 4, ee = t & 15;
        float s = 0.f;
#pragma unroll
        for (int d = 0; d < 16; d++) s += bbase[hh*16 + d] * srel[hh*256 + d*16 + ee];
        bc[t] = s * sscale[hh];
    }
}

// ---------------- job descriptors ----------------
struct TileW { const float* W; const float* b; __half* Y; };
struct JobA  { const float* X; int M; int blk0; int nT; TileW tl[5]; };
struct ParamsA { JobA job[3]; int nblk_gemm; };

struct JobE {
    const float* num0; const float* den0;
    const float* num1; const float* den1;
    const float* xold; const float* skipp;
    const float* W; const float* b; float* Y;
    int M; int blk0;
    const float* nrep; const float* drep;   // drug-dst replicas (non-null for drugs job)
};
struct ParamsE { JobE job[3]; };

struct JobI { const float* X; const float* W; const float* b; float* Y; int M; int blk0; int K; };
struct ParamsI { JobI job[3]; };

// ---------------- Phase A: TF32 -> fp16 outputs (smem-staged) + fused zeroing ----------------
__global__ void __launch_bounds__(128)
gemm_phaseA(ParamsA P)
{
    __shared__ float Xs[128 * XP];
    __shared__ float Wt[64 * WTP];
    int bx = blockIdx.x;
    int t = threadIdx.x;

    if (bx >= P.nblk_gemm) {
        int zb = bx - P.nblk_gemm;
        float4 z = make_float4(0.f, 0.f, 0.f, 0.f);
        float4* dp  = (float4*)g_den;
        float4* np  = (float4*)g_num;
        float4* drp = (float4*)g_denrepl;
        float4* nrp = (float4*)g_numrepl;
        for (int i = zb * 128 + t; i < TOTR4; i += ZB * 128) {
            if (i < DEN4)                   dp[i] = z;
            else if (i < DEN4 + NUM4)       np[i - DEN4] = z;
            else if (i < DEN4 + NUM4 + DR4) drp[i - DEN4 - NUM4] = z;
            else                            nrp[i - DEN4 - NUM4 - DR4] = z;
        }
        return;
    }

    int j = (bx >= P.job[2].blk0) ? 2 : (bx >= P.job[1].blk0) ? 1 : 0;
    const JobA& J = P.job[j];
    int m0 = (bx - J.blk0) * 128;
    const int lane = t & 31, warp = t >> 5;
    const int gid = lane >> 2, tidg = lane & 3;
    const int rb = warp * 32;

#pragma unroll
    for (int i = 0; i < 16; i++) {
        int f4 = t + i * 128;
        int row = f4 >> 4, c4 = f4 & 15;
        float4 v = make_float4(0.f, 0.f, 0.f, 0.f);
        if (m0 + row < J.M) v = *(const float4*)&J.X[(size_t)(m0 + row) * 64 + c4 * 4];
        v.x = tf32r(v.x); v.y = tf32r(v.y); v.z = tf32r(v.z); v.w = tf32r(v.w);
        *(float4*)&Xs[row * XP + c4 * 4] = v;
    }

    for (int ti = 0; ti < J.nT; ti++) {
        __syncthreads();
        const float* __restrict__ W = J.tl[ti].W;
#pragma unroll 8
        for (int i = 0; i < 32; i++) {
            int idx = t + i * 128;
            int k = idx >> 6, n = idx & 63;
            Wt[n * WTP + k] = tf32r(W[idx]);
        }
        __syncthreads();

        float acc[2][8][4];
#pragma unroll
        for (int mt = 0; mt < 2; mt++)
#pragma unroll
            for (int nt = 0; nt < 8; nt++)
#pragma unroll
                for (int r = 0; r < 4; r++) acc[mt][nt][r] = 0.f;

        tf32_mma(Xs, Wt, rb, gid, tidg, acc);

        const float* bias = J.tl[ti].b;
        float bb[16];
#pragma unroll
        for (int nt = 0; nt < 8; nt++) {
            bb[2*nt]     = bias[nt * 8 + tidg * 2];
            bb[2*nt + 1] = bias[nt * 8 + tidg * 2 + 1];
        }

        __syncthreads();
        __half* stg = (__half*)Wt;
#pragma unroll
        for (int mt = 0; mt < 2; mt++) {
#pragma unroll
            for (int rr = 0; rr < 2; rr++) {
                int rl = rb + mt * 16 + rr * 8 + gid;
#pragma unroll
                for (int nt = 0; nt < 8; nt++) {
                    float v0 = acc[mt][nt][2*rr]     + bb[2*nt];
                    float v1 = acc[mt][nt][2*rr + 1] + bb[2*nt + 1];
                    int col = (nt * 8 + tidg * 2) ^ ((rl & 7) * 8);
                    *(__half2*)&stg[rl * 64 + col] = __floats2half2_rn(v0, v1);
                }
            }
        }
        __syncthreads();

        __half* Y = J.tl[ti].Y;
#pragma unroll
        for (int i = 0; i < 8; i++) {
            int idx = t + i * 128;
            int row = idx >> 3, c8 = idx & 7;
            uint4 val = *(const uint4*)&stg[row * 64 + ((c8 * 8) ^ ((row & 7) * 8))];
            if (m0 + row < J.M)
                *(uint4*)&Y[(size_t)(m0 + row) * 64 + c8 * 8] = val;
        }
    }
}

// ---------------- Epilogue (fp32 FFMA2; hoisted reciprocals + replica sums) ----------------
__global__ void __launch_bounds__(128)
gemm_epilogue(ParamsE P)
{
    __shared__ float Xs[128 * XP];
    __shared__ __align__(16) float Ws[64 * 64];
    __shared__ float sinv[128 * 8];
    int bx = blockIdx.x;
    int j = (bx >= P.job[2].blk0) ? 2 : (bx >= P.job[1].blk0) ? 1 : 0;
    const JobE& J = P.job[j];
    int m0 = (bx - J.blk0) * 128;
    int t = threadIdx.x;
    const int ty = t >> 3, tx = t & 7;

#pragma unroll
    for (int i = 0; i < 4; i++) {
        int idx = t + i * 128;
        int row = idx >> 2, h = idx & 3;
        int n = m0 + row;
        float v0 = 0.f, v1 = 0.f;
        if (n < J.M) {
            float d0 = J.den0[(size_t)n * 4 + h];
            if (J.drep)
                for (int r = 0; r < NREP; r++)
                    d0 += J.drep[(size_t)r * N_D * 4 + (size_t)n * 4 + h];
            v0 = 1.0f / (d0 + 1e-16f);
            if (J.den1) v1 = 1.0f / (J.den1[(size_t)n * 4 + h] + 1e-16f);
        }
        sinv[row * 8 + h]     = v0;
        sinv[row * 8 + 4 + h] = v1;
    }
    __syncthreads();

#pragma unroll
    for (int i = 0; i < 16; i++) {
        int idx = t + i * 128;
        int row = idx >> 4, c4 = idx & 15;
        int n = m0 + row;
        float4 v = make_float4(0.f, 0.f, 0.f, 0.f);
        if (n < J.M) {
            int h = c4 >> 2;
            float inv0 = sinv[row * 8 + h];
            float4 a = *(const float4*)&J.num0[(size_t)n * 64 + c4 * 4];
            if (J.nrep)
                for (int r = 0; r < NREP; r++) {
                    float4 rr = *(const float4*)&J.nrep[(size_t)r * N_D * 64 + (size_t)n * 64 + c4 * 4];
                    a.x += rr.x; a.y += rr.y; a.z += rr.z; a.w += rr.w;
                }
            v.x = a.x * inv0; v.y = a.y * inv0; v.z = a.z * inv0; v.w = a.w * inv0;
            if (J.num1) {
                float inv1 = sinv[row * 8 + 4 + h];
                float4 b = *(const float4*)&J.num1[(size_t)n * 64 + c4 * 4];
                v.x += b.x * inv1; v.y += b.y * inv1;
                v.z += b.z * inv1; v.w += b.w * inv1;
            }
            v.x = gelu_exact(v.x); v.y = gelu_exact(v.y);
            v.z = gelu_exact(v.z); v.w = gelu_exact(v.w);
        }
        *(float4*)&Xs[row * XP + c4 * 4] = v;
    }
#pragma unroll
    for (int i = 0; i < 8; i++) {
        int f4 = (t + i * 128) * 4;
        *(float4*)&Ws[f4] = *(const float4*)&J.W[f4];
    }
    __syncthreads();

    u64 acc[8][4];
#pragma unroll
    for (int i = 0; i < 8; i++)
#pragma unroll
        for (int k = 0; k < 4; k++) acc[i][k] = 0ull;

    mma_core(Xs, Ws, ty, tx, acc);

    float bb[8];
#pragma unroll
    for (int q = 0; q < 8; q++) bb[q] = J.b[tx * 8 + q];
    float s = 1.0f / (1.0f + expf(-J.skipp[0]));
    float om = 1.0f - s;

#pragma unroll
    for (int i = 0; i < 8; i++) {
        int row = m0 + ty + i * 16;
        if (row < J.M) {
            float o[8];
#pragma unroll
            for (int k = 0; k < 4; k++) {
                float2 p = unpack2(acc[i][k]);
                o[2*k] = p.x + bb[2*k]; o[2*k+1] = p.y + bb[2*k+1];
            }
            float4 x0 = *(const float4*)&J.xold[(size_t)row * 64 + tx * 8];
            float4 x1 = *(const float4*)&J.xold[(size_t)row * 64 + tx * 8 + 4];
            o[0] = s*o[0] + om*x0.x; o[1] = s*o[1] + om*x0.y;
            o[2] = s*o[2] + om*x0.z; o[3] = s*o[3] + om*x0.w;
            o[4] = s*o[4] + om*x1.x; o[5] = s*o[5] + om*x1.y;
            o[6] = s*o[6] + om*x1.z; o[7] = s*o[7] + om*x1.w;
            *(float4*)&J.Y[(size_t)row * 64 + tx * 8]     = make_float4(o[0], o[1], o[2], o[3]);
            *(float4*)&J.Y[(size_t)row * 64 + tx * 8 + 4] = make_float4(o[4], o[5], o[6], o[7]);
        }
    }
}

// ---------------- Input projections: TF32 (runtime K, fp32 out) ----------------
__global__ void __launch_bounds__(128)
gemm_input(ParamsI P)
{
    __shared__ float Xs[128 * XP];
    __shared__ float Wt[64 * WTP];
    int bx = blockIdx.x;
    int j = (bx >= P.job[2].blk0) ? 2 : (bx >= P.job[1].blk0) ? 1 : 0;
    const JobI& J = P.job[j];
    int m0 = (bx - J.blk0) * 128;
    int t = threadIdx.x;
    const int lane = t & 31, warp = t >> 5;
    const int gid = lane >> 2, tidg = lane & 3;
    const int rb = warp * 32;
    const int K = J.K;

    float acc[2][8][4];
#pragma unroll
    for (int mt = 0; mt < 2; mt++)
#pragma unroll
        for (int nt = 0; nt < 8; nt++)
#pragma unroll
            for (int r = 0; r < 4; r++) acc[mt][nt][r] = 0.f;

    for (int k0 = 0; k0 < K; k0 += 64) {
        __syncthreads();
#pragma unroll
        for (int i = 0; i < 16; i++) {
            int f4 = t + i * 128;
            int row = f4 >> 4, c4 = f4 & 15;
            float4 v = make_float4(0.f, 0.f, 0.f, 0.f);
            if (m0 + row < J.M) v = *(const float4*)&J.X[(size_t)(m0 + row) * K + k0 + c4 * 4];
            v.x = tf32r(v.x); v.y = tf32r(v.y); v.z = tf32r(v.z); v.w = tf32r(v.w);
            *(float4*)&Xs[row * XP + c4 * 4] = v;
        }
#pragma unroll 8
        for (int i = 0; i < 32; i++) {
            int idx = t + i * 128;
            int k = idx >> 6, n = idx & 63;
            Wt[n * WTP + k] = tf32r(J.W[(size_t)(k0 + k) * 64 + n]);
        }
        __syncthreads();
        tf32_mma(Xs, Wt, rb, gid, tidg, acc);
    }

    float bb[16];
#pragma unroll
    for (int nt = 0; nt < 8; nt++) {
        bb[2*nt]     = J.b[nt * 8 + tidg * 2];
        bb[2*nt + 1] = J.b[nt * 8 + tidg * 2 + 1];
    }
#pragma unroll
    for (int mt = 0; mt < 2; mt++) {
#pragma unroll
        for (int rr = 0; rr < 2; rr++) {
            int row = m0 + rb + mt * 16 + rr * 8 + gid;
            if (row < J.M) {
#pragma unroll
                for (int nt = 0; nt < 8; nt++) {
                    float v0 = acc[mt][nt][2*rr]     + bb[2*nt];
                    float v1 = acc[mt][nt][2*rr + 1] + bb[2*nt + 1];
                    *(float2*)&J.Y[(size_t)row * 64 + nt * 8 + tidg * 2] = make_float2(v0, v1);
                }
            }
        }
    }
}

// ---------------- merged single-pass edge kernel (fp16 gathers, replica-split atomics) ----------------
__global__ void edge_all(const int* __restrict__ ei0, const int* __restrict__ ei1,
                         const int* __restrict__ ei2, const int* __restrict__ ei3)
{
    int gid = blockIdx.x * blockDim.x + threadIdx.x;
    if (gid >= ET * HD) return;
    int e = gid >> 2, h = gid & 3;

    const int* ei; int er, E, kvoff, qoff, dnoff;
    bool is_r0 = (e < E0);
    if (is_r0)                  { ei = ei0; er = e;            E = E0; kvoff = 0;           qoff = N_P;     dnoff = 0; }
    else if (e < E0+E1)         { ei = ei1; er = e - E0;       E = E1; kvoff = N_P;         qoff = 0;       dnoff = N_D; }
    else if (e < E0+E1+E2)      { ei = ei2; er = e - (E0+E1);  E = E2; kvoff = N_P+N_D;     qoff = N_P+N_D; dnoff = N_D+N_P; }
    else                        { ei = ei3; er = e-(E0+E1+E2); E = E3; kvoff = N_P+2*N_D;   qoff = N_P+N_D; dnoff = N_D+N_P+N_S; }

    int src = __ldg(&ei[er]);
    int dst = __ldg(&ei[E + er]);

    const uint4* qp = (const uint4*)&g_qh[(size_t)(qoff + dst) * 64 + h * 16];
    const uint4* kp = (const uint4*)&g_kh[(size_t)(kvoff + src) * 64 + h * 16];
    const uint4* vp = (const uint4*)&g_vh[(size_t)(kvoff + src) * 64 + h * 16];

    __half2 qv[8], kv[8], vv[8];
    *(uint4*)&qv[0] = qp[0]; *(uint4*)&qv[4] = qp[1];
    *(uint4*)&kv[0] = kp[0]; *(uint4*)&kv[4] = kp[1];
    *(uint4*)&vv[0] = vp[0]; *(uint4*)&vv[4] = vp[1];

    float a = 0.f;
#pragma unroll
    for (int jj = 0; jj < 8; jj++) {
        float2 qf = __half22float2(qv[jj]);
        float2 kf = __half22float2(kv[jj]);
        a += qf.x * kf.x + qf.y * kf.y;
    }
    float w = __expf(fminf(a, 60.f));

    // destination accumulator pointers (drug-dst r0 spreads over 16 replicas)
    float* denp = &g_den[(size_t)(dnoff + dst) * 4];
    float* nump = &g_num[(size_t)(dnoff + dst) * 64 + h * 16];
    if (is_r0) {
        int rep = blockIdx.x & 15;          // same for all 4 threads of an edge
        if (rep) {
            denp = &g_denrepl[(size_t)(rep - 1) * N_D * 4 + (size_t)dst * 4];
            nump = &g_numrepl[(size_t)(rep - 1) * N_D * 64 + (size_t)dst * 64 + h * 16];
        }
    }

    float w1 = __shfl_sync(0xFFFFFFFFu, w, 1, 4);
    float w2 = __shfl_sync(0xFFFFFFFFu, w, 2, 4);
    float w3 = __shfl_sync(0xFFFFFFFFu, w, 3, 4);
    if (h == 0)
        atomicAdd((float4*)denp, make_float4(w, w1, w2, w3));

    float4* np = (float4*)nump;
#pragma unroll
    for (int jj = 0; jj < 4; jj++) {
        float2 v0 = __half22float2(vv[2*jj]);
        float2 v1 = __half22float2(vv[2*jj + 1]);
        atomicAdd(&np[jj], make_float4(v0.x * w, v0.y * w, v1.x * w, v1.y * w));
    }
}

// ---------------- host orchestration ----------------
static inline int cdiv(int a, int b) { return (a + b - 1) / b; }

extern "C" void kernel_launch(void* const* d_in, const int* in_sizes, int n_in,
                              void* d_out, int out_size)
{
    const float* x_p   = (const float*)d_in[0];
    const float* x_d   = (const float*)d_in[1];
    const float* x_s   = (const float*)d_in[2];
    const float* Win_p = (const float*)d_in[3];
    const float* bin_p = (const float*)d_in[4];
    const float* Win_d = (const float*)d_in[5];
    const float* bin_d = (const float*)d_in[6];
    const float* Win_s = (const float*)d_in[7];
    const float* bin_s = (const float*)d_in[8];
    const float* Wk    = (const float*)d_in[9];
    const float* bk    = (const float*)d_in[10];
    const float* Wq    = (const float*)d_in[11];
    const float* bq    = (const float*)d_in[12];
    const float* Wv    = (const float*)d_in[13];
    const float* bv    = (const float*)d_in[14];
    const float* Wa    = (const float*)d_in[15];
    const float* ba    = (const float*)d_in[16];
    const float* a_rel = (const float*)d_in[17];
    const float* m_rel = (const float*)d_in[18];
    const float* p_rel = (const float*)d_in[19];
    const float* skip  = (const float*)d_in[20];
    const int*   ei_pd = (const int*)d_in[21];
    const int*   ei_dp = (const int*)d_in[22];
    const int*   ei_ds = (const int*)d_in[23];
    const int*   ei_ps = (const int*)d_in[24];
    float* out = (float*)d_out;

    float *px, *pnum, *pden, *pWc, *pbc, *pnr, *pdr;
    __half *pq, *pkr, *pvr;
    cudaGetSymbolAddress((void**)&px,   g_x);
    cudaGetSymbolAddress((void**)&pq,   g_qh);
    cudaGetSymbolAddress((void**)&pkr,  g_kh);
    cudaGetSymbolAddress((void**)&pvr,  g_vh);
    cudaGetSymbolAddress((void**)&pnum, g_num);
    cudaGetSymbolAddress((void**)&pden, g_den);
    cudaGetSymbolAddress((void**)&pnr,  g_numrepl);
    cudaGetSymbolAddress((void**)&pdr,  g_denrepl);
    cudaGetSymbolAddress((void**)&pWc,  g_Wc);
    cudaGetSymbolAddress((void**)&pbc,  g_bc);

    const int BP = cdiv(N_P, 128);          // 782
    const int BD = cdiv(N_D, 128);          // 8
    const int BS = cdiv(N_S, 128);          // 40
    const int NG = BP + BD + BS;            // 830
    const size_t kr0 = 0, kr1 = N_P, kr2 = N_P + N_D, kr3 = N_P + 2*N_D;

    combine_weights<<<16, 256>>>(Wk, bk, Wv, bv, a_rel, m_rel, p_rel);

    // input projections (TF32)
    {
        ParamsI P;
        P.job[0] = { x_p, Win_p, bin_p, px,                        N_P, 0,     64 };
        P.job[1] = { x_d, Win_d, bin_d, px + (size_t)N_P*64,       N_D, BP,    128 };
        P.job[2] = { x_s, Win_s, bin_s, px + (size_t)(N_P+N_D)*64, N_S, BP+BD, 64 };
        gemm_input<<<NG, 128>>>(P);
    }

    for (int l = 0; l < 2; l++) {
        // Phase A: TF32 projections (fp16 out) + fused zeroing (incl. replicas)
        {
            ParamsA P;
            P.nblk_gemm = NG;
            JobA& j0 = P.job[0];
            j0.X = px; j0.M = N_P; j0.blk0 = 0; j0.nT = 5;
            j0.tl[0] = { Wq  + (size_t)(l*3+0)*4096, bq  + (size_t)(l*3+0)*64, pq };
            j0.tl[1] = { pWc + (size_t)(l*8+0)*4096, pbc + (size_t)(l*8+0)*64, pkr + kr0*64 };
            j0.tl[2] = { pWc + (size_t)(l*8+4)*4096, pbc + (size_t)(l*8+4)*64, pvr + kr0*64 };
            j0.tl[3] = { pWc + (size_t)(l*8+3)*4096, pbc + (size_t)(l*8+3)*64, pkr + kr3*64 };
            j0.tl[4] = { pWc + (size_t)(l*8+7)*4096, pbc + (size_t)(l*8+7)*64, pvr + kr3*64 };
            JobA& j1 = P.job[1];
            j1.X = px + (size_t)N_P*64; j1.M = N_D; j1.blk0 = BP; j1.nT = 5;
            j1.tl[0] = { Wq  + (size_t)(l*3+1)*4096, bq  + (size_t)(l*3+1)*64, pq + (size_t)N_P*64 };
            j1.tl[1] = { pWc + (size_t)(l*8+1)*4096, pbc + (size_t)(l*8+1)*64, pkr + kr1*64 };
            j1.tl[2] = { pWc + (size_t)(l*8+5)*4096, pbc + (size_t)(l*8+5)*64, pvr + kr1*64 };
            j1.tl[3] = { pWc + (size_t)(l*8+2)*4096, pbc + (size_t)(l*8+2)*64, pkr + kr2*64 };
            j1.tl[4] = { pWc + (size_t)(l*8+6)*4096, pbc + (size_t)(l*8+6)*64, pvr + kr2*64 };
            JobA& j2 = P.job[2];
            j2.X = px + (size_t)(N_P+N_D)*64; j2.M = N_S; j2.blk0 = BP+BD; j2.nT = 1;
            j2.tl[0] = { Wq + (size_t)(l*3+2)*4096, bq + (size_t)(l*3+2)*64, pq + (size_t)(N_P+N_D)*64 };
            j2.tl[1] = j2.tl[0]; j2.tl[2] = j2.tl[0]; j2.tl[3] = j2.tl[0]; j2.tl[4] = j2.tl[0];
            gemm_phaseA<<<NG + ZB, 128>>>(P);
        }

        // all relations, single launch (r0 spreads over 16 accumulator replicas)
        edge_all<<<cdiv(ET * HD, 256), 256>>>(ei_pd, ei_dp, ei_ds, ei_ps);

        // epilogue (fp32 FFMA2; drug job folds in replicas)
        {
            float* Yb = (l == 0) ? px : out;
            ParamsE P;
            P.job[0] = { pnum + (size_t)N_D*64, pden + (size_t)N_D*4, nullptr, nullptr,
                         px, skip + l*3 + 0,
                         Wa + (size_t)(l*3+0)*4096, ba + (size_t)(l*3+0)*64, Yb,
                         N_P, 0, nullptr, nullptr };
            P.job[1] = { pnum, pden, nullptr, nullptr,
                         px + (size_t)N_P*64, skip + l*3 + 1,
                         Wa + (size_t)(l*3+1)*4096, ba + (size_t)(l*3+1)*64, Yb + (size_t)N_P*64,
                         N_D, BP, pnr, pdr };
            P.job[2] = { pnum + (size_t)(N_D+N_P)*64, pden + (size_t)(N_D+N_P)*4,
                         pnum + (size_t)(N_D+N_P+N_S)*64, pden + (size_t)(N_D+N_P+N_S)*4,
                         px + (size_t)(N_P+N_D)*64, skip + l*3 + 2,
                         Wa + (size_t)(l*3+2)*4096, ba + (size_t)(l*3+2)*64, Yb + (size_t)(N_P+N_D)*64,
                         N_S, BP+BD, nullptr, nullptr };
            gemm_epilogue<<<NG, 128>>>(P);
        }
    }
    (void)in_sizes; (void)n_in; (void)out_size;
}